// round 10
// baseline (speedup 1.0000x reference)
#include <cuda_runtime.h>
#include <math.h>

#define N_NODES 100000
#define F_IN    500
#define HID     64
#define NCLS    40
#define E_MAX   2000000
#define SCAN_NB ((N_NODES + 255) / 256)   // 391

// ---------------- scratch (static device globals; no allocation) ----------------
__device__ alignas(256) float g_dinv[N_NODES];
__device__ alignas(256) int   g_cnt   [N_NODES];     // in-degree (excl self-loop)
__device__ alignas(256) int   g_rowptr[N_NODES];
__device__ alignas(256) int   g_cursor[N_NODES];
__device__ alignas(256) int   g_bsum  [512];
__device__ alignas(16)  int2  g_csr   [E_MAX];       // {src, __float_as_int(norm)}
__device__ alignas(256) float g_xw1 [(size_t)N_NODES * HID];
__device__ alignas(256) float g_h   [(size_t)N_NODES * HID];
__device__ alignas(256) float g_xw2 [(size_t)N_NODES * NCLS];
__device__ alignas(256) float g_logits[(size_t)N_NODES * NCLS];

// ---------------- degree / csr build ----------------
__global__ void k_zero() {
    int i = blockIdx.x * blockDim.x + threadIdx.x;
    if (i < N_NODES) { g_cnt[i] = 0; g_cursor[i] = 0; }
}

__global__ void k_count(const int* __restrict__ src, const int* __restrict__ dst, int E) {
    int i = blockIdx.x * blockDim.x + threadIdx.x;
    if (i < E) {
        int s = src[i], d = dst[i];
        if ((unsigned)s < N_NODES && (unsigned)d < N_NODES) atomicAdd(&g_cnt[d], 1);
    }
}

__global__ void k_dinv() {
    int i = blockIdx.x * blockDim.x + threadIdx.x;
    if (i < N_NODES) g_dinv[i] = rsqrtf((float)(g_cnt[i] + 1));  // +1 self-loop
}

// block-local exclusive scan of g_cnt -> g_rowptr (partial), block totals -> g_bsum
__global__ void k_scan_local() {
    __shared__ int sh[256];
    int tid = threadIdx.x;
    int i = blockIdx.x * 256 + tid;
    int v = (i < N_NODES) ? g_cnt[i] : 0;
    sh[tid] = v;
    __syncthreads();
    #pragma unroll
    for (int off = 1; off < 256; off <<= 1) {
        int t = (tid >= off) ? sh[tid - off] : 0;
        __syncthreads();
        sh[tid] += t;
        __syncthreads();
    }
    if (i < N_NODES) g_rowptr[i] = sh[tid] - v;   // exclusive within block
    if (tid == 255) g_bsum[blockIdx.x] = sh[255];
}

// single-block exclusive scan of the 391 block sums
__global__ void k_scan_bsum() {
    __shared__ int sh[512];
    int tid = threadIdx.x;
    int v = (tid < SCAN_NB) ? g_bsum[tid] : 0;
    sh[tid] = v;
    __syncthreads();
    #pragma unroll
    for (int off = 1; off < 512; off <<= 1) {
        int t = (tid >= off) ? sh[tid - off] : 0;
        __syncthreads();
        sh[tid] += t;
        __syncthreads();
    }
    if (tid < SCAN_NB) g_bsum[tid] = sh[tid] - v;  // exclusive
}

__global__ void k_scan_add() {
    int i = blockIdx.x * 256 + threadIdx.x;
    if (i < N_NODES) g_rowptr[i] += g_bsum[blockIdx.x];
}

// scatter edges into CSR (by dst), packing {src, norm}
__global__ void k_fill(const int* __restrict__ src, const int* __restrict__ dst, int E) {
    int i = blockIdx.x * blockDim.x + threadIdx.x;
    if (i >= E) return;
    int s = src[i], d = dst[i];
    if ((unsigned)s >= N_NODES || (unsigned)d >= N_NODES) return;
    float nrm = g_dinv[s] * g_dinv[d];
    int pos = g_rowptr[d] + atomicAdd(&g_cursor[d], 1);
    g_csr[pos] = make_int2(s, __float_as_int(nrm));
}

// ---------------- GEMM1: xw1 = x @ W1 ; g_h = xw1 * dinv^2 (self-loop term) --------
#define BM 128
#define BK 32
#define XS_STRIDE 132
__global__ void k_gemm1(const float* __restrict__ x, const float* __restrict__ W1) {
    __shared__ float xs[BK * XS_STRIDE];  // transposed: xs[c*132 + r]
    __shared__ float ws[BK * HID];
    const int tid = threadIdx.x;
    const int tx = tid & 15;
    const int ty = tid >> 4;
    const int row0 = blockIdx.x * BM;

    const int lc4 = tid & 7;
    const int lr  = tid >> 3;
    const int wc4 = tid & 15;
    const int wr  = tid >> 4;

    float acc[8][4] = {};

    for (int k0 = 0; k0 < F_IN; k0 += BK) {
        #pragma unroll
        for (int i = 0; i < 4; i++) {
            int r  = lr + 32 * i;
            int gr = row0 + r;
            int gc = k0 + lc4 * 4;
            float4 v = make_float4(0.f, 0.f, 0.f, 0.f);
            if (gr < N_NODES) {
                if (gc + 3 < F_IN) {
                    v = *(const float4*)&x[(size_t)gr * F_IN + gc];
                } else {
                    float t0 = (gc + 0 < F_IN) ? x[(size_t)gr * F_IN + gc + 0] : 0.f;
                    float t1 = (gc + 1 < F_IN) ? x[(size_t)gr * F_IN + gc + 1] : 0.f;
                    float t2 = (gc + 2 < F_IN) ? x[(size_t)gr * F_IN + gc + 2] : 0.f;
                    float t3 = (gc + 3 < F_IN) ? x[(size_t)gr * F_IN + gc + 3] : 0.f;
                    v = make_float4(t0, t1, t2, t3);
                }
            }
            xs[(lc4 * 4 + 0) * XS_STRIDE + r] = v.x;
            xs[(lc4 * 4 + 1) * XS_STRIDE + r] = v.y;
            xs[(lc4 * 4 + 2) * XS_STRIDE + r] = v.z;
            xs[(lc4 * 4 + 3) * XS_STRIDE + r] = v.w;
        }
        #pragma unroll
        for (int i = 0; i < 2; i++) {
            int r  = wr + 16 * i;
            int gk = k0 + r;
            float4 v = make_float4(0.f, 0.f, 0.f, 0.f);
            if (gk < F_IN) v = *(const float4*)&W1[(size_t)gk * HID + wc4 * 4];
            *(float4*)&ws[r * HID + wc4 * 4] = v;
        }
        __syncthreads();

        #pragma unroll
        for (int kk = 0; kk < BK; kk++) {
            float4 b  = *(const float4*)&ws[kk * HID + tx * 4];
            float4 a0 = *(const float4*)&xs[kk * XS_STRIDE + ty * 8];
            float4 a1 = *(const float4*)&xs[kk * XS_STRIDE + ty * 8 + 4];
            float a[8] = {a0.x, a0.y, a0.z, a0.w, a1.x, a1.y, a1.z, a1.w};
            #pragma unroll
            for (int i = 0; i < 8; i++) {
                acc[i][0] += a[i] * b.x;
                acc[i][1] += a[i] * b.y;
                acc[i][2] += a[i] * b.z;
                acc[i][3] += a[i] * b.w;
            }
        }
        __syncthreads();
    }

    #pragma unroll
    for (int i = 0; i < 8; i++) {
        int gr = row0 + ty * 8 + i;
        if (gr < N_NODES) {
            float di = g_dinv[gr];
            float d2 = di * di;
            float4 v = make_float4(acc[i][0], acc[i][1], acc[i][2], acc[i][3]);
            *(float4*)&g_xw1[(size_t)gr * HID + tx * 4] = v;
            *(float4*)&g_h  [(size_t)gr * HID + tx * 4] =
                make_float4(v.x * d2, v.y * d2, v.z * d2, v.w * d2);
        }
    }
}

// ---------------- CSR aggregation, layer 1 -----------------------------------------
// 16 threads per node. Thread c owns column chunk c (float4) AND loads csr[beg+k0+c];
// edges are broadcast to the 16-group via shfl, so row loads batch 4-deep (MLP=4).
__global__ void k_agg1(long long nwork) {
    long long idx = (long long)blockIdx.x * blockDim.x + threadIdx.x;
    if (idx >= nwork) return;
    int node   = (int)(idx >> 4);
    int lane16 = (int)(idx & 15);
    int c      = lane16 << 2;

    int beg = g_rowptr[node];
    int n   = g_cnt[node];

    float* hp = &g_h[(size_t)node * HID + c];
    float4 acc  = *(const float4*)hp;   // self-loop term from gemm1 epilogue
    float4 acc2 = make_float4(0.f, 0.f, 0.f, 0.f);

    const unsigned FM = 0xffffffffu;
    int full = n & ~15;

    for (int k0 = 0; k0 < full; k0 += 16) {
        int2 e = g_csr[beg + k0 + lane16];
        #pragma unroll
        for (int tb = 0; tb < 16; tb += 4) {
            int   s0 = __shfl_sync(FM, e.x, tb + 0, 16);
            int   s1 = __shfl_sync(FM, e.x, tb + 1, 16);
            int   s2 = __shfl_sync(FM, e.x, tb + 2, 16);
            int   s3 = __shfl_sync(FM, e.x, tb + 3, 16);
            float n0 = __int_as_float(__shfl_sync(FM, e.y, tb + 0, 16));
            float n1 = __int_as_float(__shfl_sync(FM, e.y, tb + 1, 16));
            float n2 = __int_as_float(__shfl_sync(FM, e.y, tb + 2, 16));
            float n3 = __int_as_float(__shfl_sync(FM, e.y, tb + 3, 16));
            float4 v0 = *(const float4*)&g_xw1[(size_t)s0 * HID + c];
            float4 v1 = *(const float4*)&g_xw1[(size_t)s1 * HID + c];
            float4 v2 = *(const float4*)&g_xw1[(size_t)s2 * HID + c];
            float4 v3 = *(const float4*)&g_xw1[(size_t)s3 * HID + c];
            acc.x  = fmaf(v0.x, n0, acc.x);  acc.y  = fmaf(v0.y, n0, acc.y);
            acc.z  = fmaf(v0.z, n0, acc.z);  acc.w  = fmaf(v0.w, n0, acc.w);
            acc2.x = fmaf(v1.x, n1, acc2.x); acc2.y = fmaf(v1.y, n1, acc2.y);
            acc2.z = fmaf(v1.z, n1, acc2.z); acc2.w = fmaf(v1.w, n1, acc2.w);
            acc.x  = fmaf(v2.x, n2, acc.x);  acc.y  = fmaf(v2.y, n2, acc.y);
            acc.z  = fmaf(v2.z, n2, acc.z);  acc.w  = fmaf(v2.w, n2, acc.w);
            acc2.x = fmaf(v3.x, n3, acc2.x); acc2.y = fmaf(v3.y, n3, acc2.y);
            acc2.z = fmaf(v3.z, n3, acc2.z); acc2.w = fmaf(v3.w, n3, acc2.w);
        }
    }

    int rem = n - full;   // 0..15
    if (rem > 0) {
        int2 e = (lane16 < rem) ? g_csr[beg + full + lane16] : make_int2(0, 0);
        for (int tb = 0; tb < rem; tb += 4) {
            int   s0 = __shfl_sync(FM, e.x, tb + 0, 16);
            int   s1 = __shfl_sync(FM, e.x, tb + 1, 16);
            int   s2 = __shfl_sync(FM, e.x, tb + 2, 16);
            int   s3 = __shfl_sync(FM, e.x, tb + 3, 16);
            float n0 = __int_as_float(__shfl_sync(FM, e.y, tb + 0, 16));
            float n1 = __int_as_float(__shfl_sync(FM, e.y, tb + 1, 16));
            float n2 = __int_as_float(__shfl_sync(FM, e.y, tb + 2, 16));
            float n3 = __int_as_float(__shfl_sync(FM, e.y, tb + 3, 16));
            float4 v0 = *(const float4*)&g_xw1[(size_t)s0 * HID + c];
            float4 v1 = *(const float4*)&g_xw1[(size_t)s1 * HID + c];
            float4 v2 = *(const float4*)&g_xw1[(size_t)s2 * HID + c];
            float4 v3 = *(const float4*)&g_xw1[(size_t)s3 * HID + c];
            acc.x  = fmaf(v0.x, n0, acc.x);  acc.y  = fmaf(v0.y, n0, acc.y);
            acc.z  = fmaf(v0.z, n0, acc.z);  acc.w  = fmaf(v0.w, n0, acc.w);
            acc2.x = fmaf(v1.x, n1, acc2.x); acc2.y = fmaf(v1.y, n1, acc2.y);
            acc2.z = fmaf(v1.z, n1, acc2.z); acc2.w = fmaf(v1.w, n1, acc2.w);
            acc.x  = fmaf(v2.x, n2, acc.x);  acc.y  = fmaf(v2.y, n2, acc.y);
            acc.z  = fmaf(v2.z, n2, acc.z);  acc.w  = fmaf(v2.w, n2, acc.w);
            acc2.x = fmaf(v3.x, n3, acc2.x); acc2.y = fmaf(v3.y, n3, acc2.y);
            acc2.z = fmaf(v3.z, n3, acc2.z); acc2.w = fmaf(v3.w, n3, acc2.w);
        }
    }

    acc.x += acc2.x; acc.y += acc2.y; acc.z += acc2.z; acc.w += acc2.w;
    *(float4*)hp = acc;
}

// ---------------- GEMM2: xw2 = relu(g_h + b1) @ W2 ; g_logits = xw2 * dinv^2 -------
__global__ void k_gemm2(const float* __restrict__ W2, const float* __restrict__ b1) {
    __shared__ float ws[HID * NCLS];
    __shared__ float bs[HID];
    int tid = threadIdx.x;
    for (int i = tid; i < HID * NCLS; i += 256) ws[i] = W2[i];
    if (tid < HID) bs[tid] = b1[tid];
    __syncthreads();

    int row = blockIdx.x * 256 + tid;
    if (row >= N_NODES) return;

    float a[HID];
    const float4* hp = (const float4*)&g_h[(size_t)row * HID];
    #pragma unroll
    for (int i = 0; i < HID / 4; i++) {
        float4 v = hp[i];
        a[i * 4 + 0] = fmaxf(v.x + bs[i * 4 + 0], 0.0f);
        a[i * 4 + 1] = fmaxf(v.y + bs[i * 4 + 1], 0.0f);
        a[i * 4 + 2] = fmaxf(v.z + bs[i * 4 + 2], 0.0f);
        a[i * 4 + 3] = fmaxf(v.w + bs[i * 4 + 3], 0.0f);
    }

    float acc[NCLS] = {};
    #pragma unroll 8
    for (int k = 0; k < HID; k++) {
        float ak = a[k];
        #pragma unroll
        for (int j = 0; j < NCLS; j += 4) {
            float4 w = *(const float4*)&ws[k * NCLS + j];
            acc[j + 0] += ak * w.x;
            acc[j + 1] += ak * w.y;
            acc[j + 2] += ak * w.z;
            acc[j + 3] += ak * w.w;
        }
    }

    float di = g_dinv[row];
    float d2 = di * di;
    float4* xo = (float4*)&g_xw2[(size_t)row * NCLS];
    float4* lo = (float4*)&g_logits[(size_t)row * NCLS];
    #pragma unroll
    for (int j = 0; j < NCLS / 4; j++) {
        float4 v = make_float4(acc[j * 4 + 0], acc[j * 4 + 1], acc[j * 4 + 2], acc[j * 4 + 3]);
        xo[j] = v;
        lo[j] = make_float4(v.x * d2, v.y * d2, v.z * d2, v.w * d2);
    }
}

// ---------------- CSR aggregation, layer 2 -----------------------------------------
// Same 16-thread structure; only lanes 0..9 own a column chunk (NCLS=40 -> 10 float4).
__global__ void k_agg2(long long nwork) {
    long long idx = (long long)blockIdx.x * blockDim.x + threadIdx.x;
    if (idx >= nwork) return;
    int node   = (int)(idx >> 4);
    int lane16 = (int)(idx & 15);
    int c      = lane16 << 2;
    bool active = (lane16 < 10);

    int beg = g_rowptr[node];
    int n   = g_cnt[node];

    float* lp = &g_logits[(size_t)node * NCLS + c];
    float4 acc  = active ? *(const float4*)lp : make_float4(0.f, 0.f, 0.f, 0.f);
    float4 acc2 = make_float4(0.f, 0.f, 0.f, 0.f);

    const unsigned FM = 0xffffffffu;
    int full = n & ~15;

    for (int k0 = 0; k0 < full; k0 += 16) {
        int2 e = g_csr[beg + k0 + lane16];
        #pragma unroll
        for (int tb = 0; tb < 16; tb += 4) {
            int   s0 = __shfl_sync(FM, e.x, tb + 0, 16);
            int   s1 = __shfl_sync(FM, e.x, tb + 1, 16);
            int   s2 = __shfl_sync(FM, e.x, tb + 2, 16);
            int   s3 = __shfl_sync(FM, e.x, tb + 3, 16);
            float n0 = __int_as_float(__shfl_sync(FM, e.y, tb + 0, 16));
            float n1 = __int_as_float(__shfl_sync(FM, e.y, tb + 1, 16));
            float n2 = __int_as_float(__shfl_sync(FM, e.y, tb + 2, 16));
            float n3 = __int_as_float(__shfl_sync(FM, e.y, tb + 3, 16));
            if (active) {
                float4 v0 = *(const float4*)&g_xw2[(size_t)s0 * NCLS + c];
                float4 v1 = *(const float4*)&g_xw2[(size_t)s1 * NCLS + c];
                float4 v2 = *(const float4*)&g_xw2[(size_t)s2 * NCLS + c];
                float4 v3 = *(const float4*)&g_xw2[(size_t)s3 * NCLS + c];
                acc.x  = fmaf(v0.x, n0, acc.x);  acc.y  = fmaf(v0.y, n0, acc.y);
                acc.z  = fmaf(v0.z, n0, acc.z);  acc.w  = fmaf(v0.w, n0, acc.w);
                acc2.x = fmaf(v1.x, n1, acc2.x); acc2.y = fmaf(v1.y, n1, acc2.y);
                acc2.z = fmaf(v1.z, n1, acc2.z); acc2.w = fmaf(v1.w, n1, acc2.w);
                acc.x  = fmaf(v2.x, n2, acc.x);  acc.y  = fmaf(v2.y, n2, acc.y);
                acc.z  = fmaf(v2.z, n2, acc.z);  acc.w  = fmaf(v2.w, n2, acc.w);
                acc2.x = fmaf(v3.x, n3, acc2.x); acc2.y = fmaf(v3.y, n3, acc2.y);
                acc2.z = fmaf(v3.z, n3, acc2.z); acc2.w = fmaf(v3.w, n3, acc2.w);
            }
        }
    }

    int rem = n - full;
    if (rem > 0) {
        int2 e = (lane16 < rem) ? g_csr[beg + full + lane16] : make_int2(0, 0);
        for (int tb = 0; tb < rem; tb += 4) {
            int   s0 = __shfl_sync(FM, e.x, tb + 0, 16);
            int   s1 = __shfl_sync(FM, e.x, tb + 1, 16);
            int   s2 = __shfl_sync(FM, e.x, tb + 2, 16);
            int   s3 = __shfl_sync(FM, e.x, tb + 3, 16);
            float n0 = __int_as_float(__shfl_sync(FM, e.y, tb + 0, 16));
            float n1 = __int_as_float(__shfl_sync(FM, e.y, tb + 1, 16));
            float n2 = __int_as_float(__shfl_sync(FM, e.y, tb + 2, 16));
            float n3 = __int_as_float(__shfl_sync(FM, e.y, tb + 3, 16));
            if (active) {
                float4 v0 = *(const float4*)&g_xw2[(size_t)s0 * NCLS + c];
                float4 v1 = *(const float4*)&g_xw2[(size_t)s1 * NCLS + c];
                float4 v2 = *(const float4*)&g_xw2[(size_t)s2 * NCLS + c];
                float4 v3 = *(const float4*)&g_xw2[(size_t)s3 * NCLS + c];
                acc.x  = fmaf(v0.x, n0, acc.x);  acc.y  = fmaf(v0.y, n0, acc.y);
                acc.z  = fmaf(v0.z, n0, acc.z);  acc.w  = fmaf(v0.w, n0, acc.w);
                acc2.x = fmaf(v1.x, n1, acc2.x); acc2.y = fmaf(v1.y, n1, acc2.y);
                acc2.z = fmaf(v1.z, n1, acc2.z); acc2.w = fmaf(v1.w, n1, acc2.w);
                acc.x  = fmaf(v2.x, n2, acc.x);  acc.y  = fmaf(v2.y, n2, acc.y);
                acc.z  = fmaf(v2.z, n2, acc.z);  acc.w  = fmaf(v2.w, n2, acc.w);
                acc2.x = fmaf(v3.x, n3, acc2.x); acc2.y = fmaf(v3.y, n3, acc2.y);
                acc2.z = fmaf(v3.z, n3, acc2.z); acc2.w = fmaf(v3.w, n3, acc2.w);
            }
        }
    }

    if (active) {
        acc.x += acc2.x; acc.y += acc2.y; acc.z += acc2.z; acc.w += acc2.w;
        *(float4*)lp = acc;
    }
}

// ---------------- finalize: add b2, log_softmax, write both outputs ----------------
__global__ void k_final(const float* __restrict__ b2,
                        float* __restrict__ out_lsm,
                        float* __restrict__ out_logit) {
    int row = blockIdx.x * blockDim.x + threadIdx.x;
    if (row >= N_NODES) return;

    float v[NCLS];
    const float4* lp = (const float4*)&g_logits[(size_t)row * NCLS];
    #pragma unroll
    for (int i = 0; i < NCLS / 4; i++) {
        float4 t = lp[i];
        v[i * 4 + 0] = t.x + b2[i * 4 + 0];
        v[i * 4 + 1] = t.y + b2[i * 4 + 1];
        v[i * 4 + 2] = t.z + b2[i * 4 + 2];
        v[i * 4 + 3] = t.w + b2[i * 4 + 3];
    }

    float m = -1e30f;
    #pragma unroll
    for (int j = 0; j < NCLS; j++) m = fmaxf(m, v[j]);
    float ssum = 0.0f;
    #pragma unroll
    for (int j = 0; j < NCLS; j++) ssum += expf(v[j] - m);
    float lse = m + logf(ssum);

    #pragma unroll
    for (int j = 0; j < NCLS; j++) {
        if (out_logit) out_logit[(size_t)row * NCLS + j] = v[j];
        out_lsm[(size_t)row * NCLS + j] = v[j] - lse;
    }
}

// ---------------- launch ----------------
extern "C" void kernel_launch(void* const* d_in, const int* in_sizes, int n_in,
                              void* d_out, int out_size) {
    const float* x   = (const float*)d_in[0];
    const int*   ei  = (const int*)d_in[1];   // edge_index is int32
    const float* W1  = (const float*)d_in[2];
    const float* b1  = (const float*)d_in[3];
    const float* W2  = (const float*)d_in[4];
    const float* b2  = (const float*)d_in[5];

    const int E = in_sizes[1] / 2;
    const int* srcp = ei;
    const int* dstp = ei + E;

    float* out = (float*)d_out;
    float* out_lsm = out;
    float* out_logit = nullptr;
    if (out_size >= 2 * N_NODES * NCLS) {
        out_logit = out + (size_t)N_NODES * NCLS;
    }

    const int T = 256;
    const int nodeBlocks = (N_NODES + T - 1) / T;
    const int edgeBlocks = (E + T - 1) / T;

    // CSR build
    k_zero      <<<nodeBlocks, T>>>();
    k_count     <<<edgeBlocks, T>>>(srcp, dstp, E);
    k_dinv      <<<nodeBlocks, T>>>();
    k_scan_local<<<SCAN_NB, 256>>>();
    k_scan_bsum <<<1, 512>>>();
    k_scan_add  <<<SCAN_NB, 256>>>();
    k_fill      <<<edgeBlocks, T>>>(srcp, dstp, E);

    // layer 1
    k_gemm1<<<(N_NODES + BM - 1) / BM, 256>>>(x, W1);
    long long w1 = (long long)N_NODES * 16;
    k_agg1<<<(int)((w1 + T - 1) / T), T>>>(w1);

    // layer 2
    k_gemm2<<<nodeBlocks, T>>>(W2, b1);
    long long w2 = (long long)N_NODES * 16;
    k_agg2<<<(int)((w2 + T - 1) / T), T>>>(w2);

    k_final<<<nodeBlocks, T>>>(b2, out_lsm, out_logit);
}

// round 11
// speedup vs baseline: 1.3471x; 1.3471x over previous
#include <cuda_runtime.h>
#include <math.h>

#define N_NODES 100000
#define F_IN    500
#define HID     64
#define NCLS    40
#define E_MAX   2000000
#define SCAN_NB ((N_NODES + 255) / 256)   // 391

// ---------------- scratch (static device globals; no allocation) ----------------
__device__ alignas(256) float g_dinv[N_NODES];
__device__ alignas(256) int   g_cnt   [N_NODES];     // in-degree (excl self-loop)
__device__ alignas(256) int   g_rowptr[N_NODES];
__device__ alignas(256) int   g_cursor[N_NODES];
__device__ alignas(256) int   g_bsum  [512];
__device__ alignas(16)  int2  g_csr   [E_MAX];       // {src, __float_as_int(norm)}
__device__ alignas(256) float g_xw1 [(size_t)N_NODES * HID];
__device__ alignas(256) float g_h   [(size_t)N_NODES * HID];
__device__ alignas(256) float g_xw2 [(size_t)N_NODES * NCLS];
__device__ alignas(256) float g_logits[(size_t)N_NODES * NCLS];

// ---------------- degree / csr build ----------------
__global__ void k_zero() {
    int i = blockIdx.x * blockDim.x + threadIdx.x;
    if (i < N_NODES) { g_cnt[i] = 0; g_cursor[i] = 0; }
}

__global__ void k_count(const int* __restrict__ src, const int* __restrict__ dst, int E) {
    int i = blockIdx.x * blockDim.x + threadIdx.x;
    if (i < E) {
        int s = src[i], d = dst[i];
        if ((unsigned)s < N_NODES && (unsigned)d < N_NODES) atomicAdd(&g_cnt[d], 1);
    }
}

__global__ void k_dinv() {
    int i = blockIdx.x * blockDim.x + threadIdx.x;
    if (i < N_NODES) g_dinv[i] = rsqrtf((float)(g_cnt[i] + 1));  // +1 self-loop
}

// block-local exclusive scan of g_cnt -> g_rowptr (partial), block totals -> g_bsum
__global__ void k_scan_local() {
    __shared__ int sh[256];
    int tid = threadIdx.x;
    int i = blockIdx.x * 256 + tid;
    int v = (i < N_NODES) ? g_cnt[i] : 0;
    sh[tid] = v;
    __syncthreads();
    #pragma unroll
    for (int off = 1; off < 256; off <<= 1) {
        int t = (tid >= off) ? sh[tid - off] : 0;
        __syncthreads();
        sh[tid] += t;
        __syncthreads();
    }
    if (i < N_NODES) g_rowptr[i] = sh[tid] - v;   // exclusive within block
    if (tid == 255) g_bsum[blockIdx.x] = sh[255];
}

// single-block exclusive scan of the 391 block sums
__global__ void k_scan_bsum() {
    __shared__ int sh[512];
    int tid = threadIdx.x;
    int v = (tid < SCAN_NB) ? g_bsum[tid] : 0;
    sh[tid] = v;
    __syncthreads();
    #pragma unroll
    for (int off = 1; off < 512; off <<= 1) {
        int t = (tid >= off) ? sh[tid - off] : 0;
        __syncthreads();
        sh[tid] += t;
        __syncthreads();
    }
    if (tid < SCAN_NB) g_bsum[tid] = sh[tid] - v;  // exclusive
}

__global__ void k_scan_add() {
    int i = blockIdx.x * 256 + threadIdx.x;
    if (i < N_NODES) g_rowptr[i] += g_bsum[blockIdx.x];
}

// scatter edges into CSR (by dst), packing {src, norm}
__global__ void k_fill(const int* __restrict__ src, const int* __restrict__ dst, int E) {
    int i = blockIdx.x * blockDim.x + threadIdx.x;
    if (i >= E) return;
    int s = src[i], d = dst[i];
    if ((unsigned)s >= N_NODES || (unsigned)d >= N_NODES) return;
    float nrm = g_dinv[s] * g_dinv[d];
    int pos = g_rowptr[d] + atomicAdd(&g_cursor[d], 1);
    g_csr[pos] = make_int2(s, __float_as_int(nrm));
}

// ---------------- GEMM1: xw1 = x @ W1 ; g_h = xw1 * dinv^2 (self-loop term) --------
#define BM 128
#define BK 32
#define XS_STRIDE 132
__global__ void k_gemm1(const float* __restrict__ x, const float* __restrict__ W1) {
    __shared__ float xs[BK * XS_STRIDE];  // transposed: xs[c*132 + r]
    __shared__ float ws[BK * HID];
    const int tid = threadIdx.x;
    const int tx = tid & 15;
    const int ty = tid >> 4;
    const int row0 = blockIdx.x * BM;

    const int lc4 = tid & 7;
    const int lr  = tid >> 3;
    const int wc4 = tid & 15;
    const int wr  = tid >> 4;

    float acc[8][4] = {};

    for (int k0 = 0; k0 < F_IN; k0 += BK) {
        #pragma unroll
        for (int i = 0; i < 4; i++) {
            int r  = lr + 32 * i;
            int gr = row0 + r;
            int gc = k0 + lc4 * 4;
            float4 v = make_float4(0.f, 0.f, 0.f, 0.f);
            if (gr < N_NODES) {
                if (gc + 3 < F_IN) {
                    v = *(const float4*)&x[(size_t)gr * F_IN + gc];
                } else {
                    float t0 = (gc + 0 < F_IN) ? x[(size_t)gr * F_IN + gc + 0] : 0.f;
                    float t1 = (gc + 1 < F_IN) ? x[(size_t)gr * F_IN + gc + 1] : 0.f;
                    float t2 = (gc + 2 < F_IN) ? x[(size_t)gr * F_IN + gc + 2] : 0.f;
                    float t3 = (gc + 3 < F_IN) ? x[(size_t)gr * F_IN + gc + 3] : 0.f;
                    v = make_float4(t0, t1, t2, t3);
                }
            }
            xs[(lc4 * 4 + 0) * XS_STRIDE + r] = v.x;
            xs[(lc4 * 4 + 1) * XS_STRIDE + r] = v.y;
            xs[(lc4 * 4 + 2) * XS_STRIDE + r] = v.z;
            xs[(lc4 * 4 + 3) * XS_STRIDE + r] = v.w;
        }
        #pragma unroll
        for (int i = 0; i < 2; i++) {
            int r  = wr + 16 * i;
            int gk = k0 + r;
            float4 v = make_float4(0.f, 0.f, 0.f, 0.f);
            if (gk < F_IN) v = *(const float4*)&W1[(size_t)gk * HID + wc4 * 4];
            *(float4*)&ws[r * HID + wc4 * 4] = v;
        }
        __syncthreads();

        #pragma unroll
        for (int kk = 0; kk < BK; kk++) {
            float4 b  = *(const float4*)&ws[kk * HID + tx * 4];
            float4 a0 = *(const float4*)&xs[kk * XS_STRIDE + ty * 8];
            float4 a1 = *(const float4*)&xs[kk * XS_STRIDE + ty * 8 + 4];
            float a[8] = {a0.x, a0.y, a0.z, a0.w, a1.x, a1.y, a1.z, a1.w};
            #pragma unroll
            for (int i = 0; i < 8; i++) {
                acc[i][0] += a[i] * b.x;
                acc[i][1] += a[i] * b.y;
                acc[i][2] += a[i] * b.z;
                acc[i][3] += a[i] * b.w;
            }
        }
        __syncthreads();
    }

    #pragma unroll
    for (int i = 0; i < 8; i++) {
        int gr = row0 + ty * 8 + i;
        if (gr < N_NODES) {
            float di = g_dinv[gr];
            float d2 = di * di;
            float4 v = make_float4(acc[i][0], acc[i][1], acc[i][2], acc[i][3]);
            *(float4*)&g_xw1[(size_t)gr * HID + tx * 4] = v;
            *(float4*)&g_h  [(size_t)gr * HID + tx * 4] =
                make_float4(v.x * d2, v.y * d2, v.z * d2, v.w * d2);
        }
    }
}

// ---------------- CSR aggregation, layer 1 -----------------------------------------
// 16 threads per node, one float4 column-chunk each. Uniform csr reads (L1 broadcast),
// coalesced 256B row gathers, 4-way unrolled (MLP=4), dual accumulators.
__global__ void k_agg1(long long nwork) {
    long long idx = (long long)blockIdx.x * blockDim.x + threadIdx.x;
    if (idx >= nwork) return;
    int node = (int)(idx >> 4);
    int c = (int)(idx & 15) << 2;

    int beg = g_rowptr[node];
    int n   = g_cnt[node];

    float* hp = &g_h[(size_t)node * HID + c];
    float4 acc  = *(const float4*)hp;   // self-loop term from gemm1 epilogue
    float4 acc2 = make_float4(0.f, 0.f, 0.f, 0.f);

    int j = 0;
    for (; j + 3 < n; j += 4) {
        int2 e0 = g_csr[beg + j + 0];
        int2 e1 = g_csr[beg + j + 1];
        int2 e2 = g_csr[beg + j + 2];
        int2 e3 = g_csr[beg + j + 3];
        float4 v0 = __ldg((const float4*)&g_xw1[(size_t)e0.x * HID + c]);
        float4 v1 = __ldg((const float4*)&g_xw1[(size_t)e1.x * HID + c]);
        float4 v2 = __ldg((const float4*)&g_xw1[(size_t)e2.x * HID + c]);
        float4 v3 = __ldg((const float4*)&g_xw1[(size_t)e3.x * HID + c]);
        float n0 = __int_as_float(e0.y);
        float n1 = __int_as_float(e1.y);
        float n2 = __int_as_float(e2.y);
        float n3 = __int_as_float(e3.y);
        acc.x  = fmaf(v0.x, n0, acc.x);  acc.y  = fmaf(v0.y, n0, acc.y);
        acc.z  = fmaf(v0.z, n0, acc.z);  acc.w  = fmaf(v0.w, n0, acc.w);
        acc2.x = fmaf(v1.x, n1, acc2.x); acc2.y = fmaf(v1.y, n1, acc2.y);
        acc2.z = fmaf(v1.z, n1, acc2.z); acc2.w = fmaf(v1.w, n1, acc2.w);
        acc.x  = fmaf(v2.x, n2, acc.x);  acc.y  = fmaf(v2.y, n2, acc.y);
        acc.z  = fmaf(v2.z, n2, acc.z);  acc.w  = fmaf(v2.w, n2, acc.w);
        acc2.x = fmaf(v3.x, n3, acc2.x); acc2.y = fmaf(v3.y, n3, acc2.y);
        acc2.z = fmaf(v3.z, n3, acc2.z); acc2.w = fmaf(v3.w, n3, acc2.w);
    }
    for (; j < n; j++) {
        int2 e0 = g_csr[beg + j];
        float4 v0 = __ldg((const float4*)&g_xw1[(size_t)e0.x * HID + c]);
        float n0 = __int_as_float(e0.y);
        acc.x = fmaf(v0.x, n0, acc.x);
        acc.y = fmaf(v0.y, n0, acc.y);
        acc.z = fmaf(v0.z, n0, acc.z);
        acc.w = fmaf(v0.w, n0, acc.w);
    }

    acc.x += acc2.x; acc.y += acc2.y; acc.z += acc2.z; acc.w += acc2.w;
    *(float4*)hp = acc;
}

// ---------------- GEMM2: xw2 = relu(g_h + b1) @ W2 ; g_logits = xw2 * dinv^2 -------
__global__ void k_gemm2(const float* __restrict__ W2, const float* __restrict__ b1) {
    __shared__ float ws[HID * NCLS];
    __shared__ float bs[HID];
    int tid = threadIdx.x;
    for (int i = tid; i < HID * NCLS; i += 256) ws[i] = W2[i];
    if (tid < HID) bs[tid] = b1[tid];
    __syncthreads();

    int row = blockIdx.x * 256 + tid;
    if (row >= N_NODES) return;

    float a[HID];
    const float4* hp = (const float4*)&g_h[(size_t)row * HID];
    #pragma unroll
    for (int i = 0; i < HID / 4; i++) {
        float4 v = hp[i];
        a[i * 4 + 0] = fmaxf(v.x + bs[i * 4 + 0], 0.0f);
        a[i * 4 + 1] = fmaxf(v.y + bs[i * 4 + 1], 0.0f);
        a[i * 4 + 2] = fmaxf(v.z + bs[i * 4 + 2], 0.0f);
        a[i * 4 + 3] = fmaxf(v.w + bs[i * 4 + 3], 0.0f);
    }

    float acc[NCLS] = {};
    #pragma unroll 8
    for (int k = 0; k < HID; k++) {
        float ak = a[k];
        #pragma unroll
        for (int j = 0; j < NCLS; j += 4) {
            float4 w = *(const float4*)&ws[k * NCLS + j];
            acc[j + 0] += ak * w.x;
            acc[j + 1] += ak * w.y;
            acc[j + 2] += ak * w.z;
            acc[j + 3] += ak * w.w;
        }
    }

    float di = g_dinv[row];
    float d2 = di * di;
    float4* xo = (float4*)&g_xw2[(size_t)row * NCLS];
    float4* lo = (float4*)&g_logits[(size_t)row * NCLS];
    #pragma unroll
    for (int j = 0; j < NCLS / 4; j++) {
        float4 v = make_float4(acc[j * 4 + 0], acc[j * 4 + 1], acc[j * 4 + 2], acc[j * 4 + 3]);
        xo[j] = v;
        lo[j] = make_float4(v.x * d2, v.y * d2, v.z * d2, v.w * d2);
    }
}

// ---------------- CSR aggregation, layer 2 + fused bias/log_softmax ----------------
// 16 threads per node; lanes 0..9 own float4 column chunks (NCLS=40). After the
// gather-accumulate, add b2 and do log_softmax via width-16 shfl reductions.
__global__ void k_agg2(const float* __restrict__ b2,
                       float* __restrict__ out_lsm,
                       float* __restrict__ out_logit,
                       long long nwork) {
    long long idx = (long long)blockIdx.x * blockDim.x + threadIdx.x;
    if (idx >= nwork) return;
    int node   = (int)(idx >> 4);
    int lane16 = (int)(idx & 15);
    int c      = lane16 << 2;
    bool active = (lane16 < 10);

    int beg = g_rowptr[node];
    int n   = g_cnt[node];

    float4 acc  = active ? *(const float4*)&g_logits[(size_t)node * NCLS + c]
                         : make_float4(0.f, 0.f, 0.f, 0.f);
    float4 acc2 = make_float4(0.f, 0.f, 0.f, 0.f);

    if (active) {
        int j = 0;
        for (; j + 3 < n; j += 4) {
            int2 e0 = g_csr[beg + j + 0];
            int2 e1 = g_csr[beg + j + 1];
            int2 e2 = g_csr[beg + j + 2];
            int2 e3 = g_csr[beg + j + 3];
            float4 v0 = __ldg((const float4*)&g_xw2[(size_t)e0.x * NCLS + c]);
            float4 v1 = __ldg((const float4*)&g_xw2[(size_t)e1.x * NCLS + c]);
            float4 v2 = __ldg((const float4*)&g_xw2[(size_t)e2.x * NCLS + c]);
            float4 v3 = __ldg((const float4*)&g_xw2[(size_t)e3.x * NCLS + c]);
            float n0 = __int_as_float(e0.y);
            float n1 = __int_as_float(e1.y);
            float n2 = __int_as_float(e2.y);
            float n3 = __int_as_float(e3.y);
            acc.x  = fmaf(v0.x, n0, acc.x);  acc.y  = fmaf(v0.y, n0, acc.y);
            acc.z  = fmaf(v0.z, n0, acc.z);  acc.w  = fmaf(v0.w, n0, acc.w);
            acc2.x = fmaf(v1.x, n1, acc2.x); acc2.y = fmaf(v1.y, n1, acc2.y);
            acc2.z = fmaf(v1.z, n1, acc2.z); acc2.w = fmaf(v1.w, n1, acc2.w);
            acc.x  = fmaf(v2.x, n2, acc.x);  acc.y  = fmaf(v2.y, n2, acc.y);
            acc.z  = fmaf(v2.z, n2, acc.z);  acc.w  = fmaf(v2.w, n2, acc.w);
            acc2.x = fmaf(v3.x, n3, acc2.x); acc2.y = fmaf(v3.y, n3, acc2.y);
            acc2.z = fmaf(v3.z, n3, acc2.z); acc2.w = fmaf(v3.w, n3, acc2.w);
        }
        for (; j < n; j++) {
            int2 e0 = g_csr[beg + j];
            float4 v0 = __ldg((const float4*)&g_xw2[(size_t)e0.x * NCLS + c]);
            float n0 = __int_as_float(e0.y);
            acc.x = fmaf(v0.x, n0, acc.x);
            acc.y = fmaf(v0.y, n0, acc.y);
            acc.z = fmaf(v0.z, n0, acc.z);
            acc.w = fmaf(v0.w, n0, acc.w);
        }
        acc.x += acc2.x; acc.y += acc2.y; acc.z += acc2.z; acc.w += acc2.w;
        // add bias
        float4 bv = *(const float4*)&b2[c];
        acc.x += bv.x; acc.y += bv.y; acc.z += bv.z; acc.w += bv.w;
    }

    // ---- fused log_softmax over the node's 40 logits (width-16 shfl) ----
    const unsigned FM = 0xffffffffu;
    float lmax = active ? fmaxf(fmaxf(acc.x, acc.y), fmaxf(acc.z, acc.w)) : -INFINITY;
    #pragma unroll
    for (int off = 8; off > 0; off >>= 1)
        lmax = fmaxf(lmax, __shfl_xor_sync(FM, lmax, off, 16));

    float lsum = 0.0f;
    if (active) {
        lsum = expf(acc.x - lmax) + expf(acc.y - lmax)
             + expf(acc.z - lmax) + expf(acc.w - lmax);
    }
    #pragma unroll
    for (int off = 8; off > 0; off >>= 1)
        lsum += __shfl_xor_sync(FM, lsum, off, 16);

    float lse = lmax + logf(lsum);

    if (active) {
        if (out_logit)
            *(float4*)&out_logit[(size_t)node * NCLS + c] = acc;
        *(float4*)&out_lsm[(size_t)node * NCLS + c] =
            make_float4(acc.x - lse, acc.y - lse, acc.z - lse, acc.w - lse);
    }
}

// ---------------- launch ----------------
extern "C" void kernel_launch(void* const* d_in, const int* in_sizes, int n_in,
                              void* d_out, int out_size) {
    const float* x   = (const float*)d_in[0];
    const int*   ei  = (const int*)d_in[1];   // edge_index is int32
    const float* W1  = (const float*)d_in[2];
    const float* b1  = (const float*)d_in[3];
    const float* W2  = (const float*)d_in[4];
    const float* b2  = (const float*)d_in[5];

    const int E = in_sizes[1] / 2;
    const int* srcp = ei;
    const int* dstp = ei + E;

    float* out = (float*)d_out;
    float* out_lsm = out;
    float* out_logit = nullptr;
    if (out_size >= 2 * N_NODES * NCLS) {
        out_logit = out + (size_t)N_NODES * NCLS;
    }

    const int T = 256;
    const int nodeBlocks = (N_NODES + T - 1) / T;
    const int edgeBlocks = (E + T - 1) / T;

    // CSR build
    k_zero      <<<nodeBlocks, T>>>();
    k_count     <<<edgeBlocks, T>>>(srcp, dstp, E);
    k_dinv      <<<nodeBlocks, T>>>();
    k_scan_local<<<SCAN_NB, 256>>>();
    k_scan_bsum <<<1, 512>>>();
    k_scan_add  <<<SCAN_NB, 256>>>();
    k_fill      <<<edgeBlocks, T>>>(srcp, dstp, E);

    // layer 1
    k_gemm1<<<(N_NODES + BM - 1) / BM, 256>>>(x, W1);
    long long w1 = (long long)N_NODES * 16;
    k_agg1<<<(int)((w1 + T - 1) / T), T>>>(w1);

    // layer 2 (agg2 fuses bias + log_softmax + output writes)
    k_gemm2<<<nodeBlocks, T>>>(W2, b1);
    long long w2 = (long long)N_NODES * 16;
    k_agg2<<<(int)((w2 + T - 1) / T), T>>>(b2, out_lsm, out_logit, w2);
}

// round 13
// speedup vs baseline: 1.5917x; 1.1815x over previous
#include <cuda_runtime.h>
#include <math.h>
#include <stdint.h>

#define N_NODES 100000
#define F_IN    500
#define HID     64
#define NCLS    40
#define E_MAX   2000000
#define SCAN_NB ((N_NODES + 255) / 256)   // 391

// ---------------- scratch (static device globals; no allocation) ----------------
__device__ alignas(256) float g_dinv[N_NODES];
__device__ alignas(256) int   g_cnt   [N_NODES];     // in-degree (excl self-loop)
__device__ alignas(256) int   g_rowptr[N_NODES];
__device__ alignas(256) int   g_cursor[N_NODES];
__device__ alignas(256) int   g_bsum  [512];
__device__ alignas(16)  int2  g_csr   [E_MAX];       // {src, __float_as_int(norm)}
__device__ alignas(256) float g_xw1 [(size_t)N_NODES * HID];
__device__ alignas(256) float g_h   [(size_t)N_NODES * HID];
__device__ alignas(256) float g_xw2 [(size_t)N_NODES * NCLS];
__device__ alignas(256) float g_logits[(size_t)N_NODES * NCLS];

// ---------------- degree / csr build ----------------
__global__ void k_zero() {
    int i = blockIdx.x * blockDim.x + threadIdx.x;
    if (i < N_NODES) { g_cnt[i] = 0; g_cursor[i] = 0; }
}

__global__ void k_count(const int* __restrict__ src, const int* __restrict__ dst, int E) {
    int i = blockIdx.x * blockDim.x + threadIdx.x;
    if (i < E) {
        int s = src[i], d = dst[i];
        if ((unsigned)s < N_NODES && (unsigned)d < N_NODES) atomicAdd(&g_cnt[d], 1);
    }
}

__global__ void k_dinv() {
    int i = blockIdx.x * blockDim.x + threadIdx.x;
    if (i < N_NODES) g_dinv[i] = rsqrtf((float)(g_cnt[i] + 1));  // +1 self-loop
}

__global__ void k_scan_local() {
    __shared__ int sh[256];
    int tid = threadIdx.x;
    int i = blockIdx.x * 256 + tid;
    int v = (i < N_NODES) ? g_cnt[i] : 0;
    sh[tid] = v;
    __syncthreads();
    #pragma unroll
    for (int off = 1; off < 256; off <<= 1) {
        int t = (tid >= off) ? sh[tid - off] : 0;
        __syncthreads();
        sh[tid] += t;
        __syncthreads();
    }
    if (i < N_NODES) g_rowptr[i] = sh[tid] - v;
    if (tid == 255) g_bsum[blockIdx.x] = sh[255];
}

__global__ void k_scan_bsum() {
    __shared__ int sh[512];
    int tid = threadIdx.x;
    int v = (tid < SCAN_NB) ? g_bsum[tid] : 0;
    sh[tid] = v;
    __syncthreads();
    #pragma unroll
    for (int off = 1; off < 512; off <<= 1) {
        int t = (tid >= off) ? sh[tid - off] : 0;
        __syncthreads();
        sh[tid] += t;
        __syncthreads();
    }
    if (tid < SCAN_NB) g_bsum[tid] = sh[tid] - v;
}

__global__ void k_scan_add() {
    int i = blockIdx.x * 256 + threadIdx.x;
    if (i < N_NODES) g_rowptr[i] += g_bsum[blockIdx.x];
}

__global__ void k_fill(const int* __restrict__ src, const int* __restrict__ dst, int E) {
    int i = blockIdx.x * blockDim.x + threadIdx.x;
    if (i >= E) return;
    int s = src[i], d = dst[i];
    if ((unsigned)s >= N_NODES || (unsigned)d >= N_NODES) return;
    float nrm = g_dinv[s] * g_dinv[d];
    int pos = g_rowptr[d] + atomicAdd(&g_cursor[d], 1);
    g_csr[pos] = make_int2(s, __float_as_int(nrm));
}

// ---------------- GEMM1 (tf32 tensor cores) ----------------------------------------
// xw1 = x @ W1 ; g_h = xw1 * dinv^2. 128x64 tile, 8 warps, each warp 16 rows x 64 cols
// via m16n8k8 tf32 mma. tf32 conversion happens once in the smem loaders.
__device__ __forceinline__ uint32_t f2tf32(float f) {
    uint32_t u;
    asm("cvt.rna.tf32.f32 %0, %1;" : "=r"(u) : "f"(f));
    return u;
}

#define XSS 36   // xs row stride (words): (4g+t) bank pattern conflict-free
#define WSS 72   // ws row stride (words): (8t+g) bank pattern conflict-free

__global__ void k_gemm1(const float* __restrict__ x, const float* __restrict__ W1) {
    __shared__ uint32_t xs[128 * XSS];  // xs[r*36 + k], tf32 bits
    __shared__ uint32_t ws[32 * WSS];   // ws[k*72 + n], tf32 bits
    const int tid  = threadIdx.x;
    const int lane = tid & 31;
    const int warp = tid >> 5;
    const int g = lane >> 2, t = lane & 3;
    const int row0 = blockIdx.x * 128;
    const int rw = warp * 16;

    float c[8][4] = {};

    for (int k0 = 0; k0 < 512; k0 += 32) {
        // ---- x tile: 128 rows x 32 cols ----
        #pragma unroll
        for (int i = 0; i < 4; i++) {
            int linear = tid + i * 256;          // float4 slot 0..1023
            int r = linear >> 3, c4 = linear & 7;
            int gr = row0 + r, gc = k0 + c4 * 4;
            float4 v = make_float4(0.f, 0.f, 0.f, 0.f);
            if (gr < N_NODES && gc < F_IN)        // F_IN%4==0 -> full float4 in-bounds
                v = *(const float4*)&x[(size_t)gr * F_IN + gc];
            uint4 u = make_uint4(f2tf32(v.x), f2tf32(v.y), f2tf32(v.z), f2tf32(v.w));
            *(uint4*)&xs[r * XSS + c4 * 4] = u;
        }
        // ---- W1 tile: 32 rows x 64 cols ----
        #pragma unroll
        for (int i = 0; i < 2; i++) {
            int linear = tid + i * 256;          // float4 slot 0..511
            int r = linear >> 4, c4 = linear & 15;
            int gk = k0 + r;
            float4 v = make_float4(0.f, 0.f, 0.f, 0.f);
            if (gk < F_IN) v = *(const float4*)&W1[(size_t)gk * HID + c4 * 4];
            uint4 u = make_uint4(f2tf32(v.x), f2tf32(v.y), f2tf32(v.z), f2tf32(v.w));
            *(uint4*)&ws[r * WSS + c4 * 4] = u;
        }
        __syncthreads();

        #pragma unroll
        for (int ks = 0; ks < 4; ks++) {
            int kb = ks * 8;
            uint32_t a0 = xs[(rw + g    ) * XSS + kb + t    ];
            uint32_t a1 = xs[(rw + g + 8) * XSS + kb + t    ];
            uint32_t a2 = xs[(rw + g    ) * XSS + kb + t + 4];
            uint32_t a3 = xs[(rw + g + 8) * XSS + kb + t + 4];
            #pragma unroll
            for (int j = 0; j < 8; j++) {
                uint32_t b0 = ws[(kb + t    ) * WSS + j * 8 + g];
                uint32_t b1 = ws[(kb + t + 4) * WSS + j * 8 + g];
                asm volatile(
                    "mma.sync.aligned.m16n8k8.row.col.f32.tf32.tf32.f32 "
                    "{%0,%1,%2,%3}, {%4,%5,%6,%7}, {%8,%9}, {%0,%1,%2,%3};"
                    : "+f"(c[j][0]), "+f"(c[j][1]), "+f"(c[j][2]), "+f"(c[j][3])
                    : "r"(a0), "r"(a1), "r"(a2), "r"(a3), "r"(b0), "r"(b1));
            }
        }
        __syncthreads();
    }

    // epilogue: c[j][0..1] -> row rw+g, cols j*8+2t..+1 ; c[j][2..3] -> row rw+g+8
    int r0 = row0 + rw + g;
    int r1 = r0 + 8;
    float d20 = 0.f, d21 = 0.f;
    if (r0 < N_NODES) { float di = g_dinv[r0]; d20 = di * di; }
    if (r1 < N_NODES) { float di = g_dinv[r1]; d21 = di * di; }
    #pragma unroll
    for (int j = 0; j < 8; j++) {
        int col = j * 8 + 2 * t;
        if (r0 < N_NODES) {
            float2 v = make_float2(c[j][0], c[j][1]);
            *(float2*)&g_xw1[(size_t)r0 * HID + col] = v;
            *(float2*)&g_h  [(size_t)r0 * HID + col] = make_float2(v.x * d20, v.y * d20);
        }
        if (r1 < N_NODES) {
            float2 v = make_float2(c[j][2], c[j][3]);
            *(float2*)&g_xw1[(size_t)r1 * HID + col] = v;
            *(float2*)&g_h  [(size_t)r1 * HID + col] = make_float2(v.x * d21, v.y * d21);
        }
    }
}

// ---------------- CSR aggregation, layer 1 -----------------------------------------
__global__ void k_agg1(long long nwork) {
    long long idx = (long long)blockIdx.x * blockDim.x + threadIdx.x;
    if (idx >= nwork) return;
    int node = (int)(idx >> 4);
    int c = (int)(idx & 15) << 2;

    int beg = g_rowptr[node];
    int n   = g_cnt[node];

    float* hp = &g_h[(size_t)node * HID + c];
    float4 acc  = *(const float4*)hp;   // self-loop term
    float4 acc2 = make_float4(0.f, 0.f, 0.f, 0.f);

    int j = 0;
    for (; j + 3 < n; j += 4) {
        int2 e0 = g_csr[beg + j + 0];
        int2 e1 = g_csr[beg + j + 1];
        int2 e2 = g_csr[beg + j + 2];
        int2 e3 = g_csr[beg + j + 3];
        float4 v0 = __ldg((const float4*)&g_xw1[(size_t)e0.x * HID + c]);
        float4 v1 = __ldg((const float4*)&g_xw1[(size_t)e1.x * HID + c]);
        float4 v2 = __ldg((const float4*)&g_xw1[(size_t)e2.x * HID + c]);
        float4 v3 = __ldg((const float4*)&g_xw1[(size_t)e3.x * HID + c]);
        float n0 = __int_as_float(e0.y);
        float n1 = __int_as_float(e1.y);
        float n2 = __int_as_float(e2.y);
        float n3 = __int_as_float(e3.y);
        acc.x  = fmaf(v0.x, n0, acc.x);  acc.y  = fmaf(v0.y, n0, acc.y);
        acc.z  = fmaf(v0.z, n0, acc.z);  acc.w  = fmaf(v0.w, n0, acc.w);
        acc2.x = fmaf(v1.x, n1, acc2.x); acc2.y = fmaf(v1.y, n1, acc2.y);
        acc2.z = fmaf(v1.z, n1, acc2.z); acc2.w = fmaf(v1.w, n1, acc2.w);
        acc.x  = fmaf(v2.x, n2, acc.x);  acc.y  = fmaf(v2.y, n2, acc.y);
        acc.z  = fmaf(v2.z, n2, acc.z);  acc.w  = fmaf(v2.w, n2, acc.w);
        acc2.x = fmaf(v3.x, n3, acc2.x); acc2.y = fmaf(v3.y, n3, acc2.y);
        acc2.z = fmaf(v3.z, n3, acc2.z); acc2.w = fmaf(v3.w, n3, acc2.w);
    }
    for (; j < n; j++) {
        int2 e0 = g_csr[beg + j];
        float4 v0 = __ldg((const float4*)&g_xw1[(size_t)e0.x * HID + c]);
        float n0 = __int_as_float(e0.y);
        acc.x = fmaf(v0.x, n0, acc.x);
        acc.y = fmaf(v0.y, n0, acc.y);
        acc.z = fmaf(v0.z, n0, acc.z);
        acc.w = fmaf(v0.w, n0, acc.w);
    }

    acc.x += acc2.x; acc.y += acc2.y; acc.z += acc2.z; acc.w += acc2.w;
    *(float4*)hp = acc;
}

// ---------------- GEMM2: xw2 = relu(g_h + b1) @ W2 ; g_logits = xw2 * dinv^2 -------
__global__ void k_gemm2(const float* __restrict__ W2, const float* __restrict__ b1) {
    __shared__ float ws[HID * NCLS];
    __shared__ float bs[HID];
    int tid = threadIdx.x;
    for (int i = tid; i < HID * NCLS; i += 256) ws[i] = W2[i];
    if (tid < HID) bs[tid] = b1[tid];
    __syncthreads();

    int row = blockIdx.x * 256 + tid;
    if (row >= N_NODES) return;

    float a[HID];
    const float4* hp = (const float4*)&g_h[(size_t)row * HID];
    #pragma unroll
    for (int i = 0; i < HID / 4; i++) {
        float4 v = hp[i];
        a[i * 4 + 0] = fmaxf(v.x + bs[i * 4 + 0], 0.0f);
        a[i * 4 + 1] = fmaxf(v.y + bs[i * 4 + 1], 0.0f);
        a[i * 4 + 2] = fmaxf(v.z + bs[i * 4 + 2], 0.0f);
        a[i * 4 + 3] = fmaxf(v.w + bs[i * 4 + 3], 0.0f);
    }

    float acc[NCLS] = {};
    #pragma unroll 8
    for (int k = 0; k < HID; k++) {
        float ak = a[k];
        #pragma unroll
        for (int j = 0; j < NCLS; j += 4) {
            float4 w = *(const float4*)&ws[k * NCLS + j];
            acc[j + 0] += ak * w.x;
            acc[j + 1] += ak * w.y;
            acc[j + 2] += ak * w.z;
            acc[j + 3] += ak * w.w;
        }
    }

    float di = g_dinv[row];
    float d2 = di * di;
    float4* xo = (float4*)&g_xw2[(size_t)row * NCLS];
    float4* lo = (float4*)&g_logits[(size_t)row * NCLS];
    #pragma unroll
    for (int j = 0; j < NCLS / 4; j++) {
        float4 v = make_float4(acc[j * 4 + 0], acc[j * 4 + 1], acc[j * 4 + 2], acc[j * 4 + 3]);
        xo[j] = v;
        lo[j] = make_float4(v.x * d2, v.y * d2, v.z * d2, v.w * d2);
    }
}

// ---------------- CSR aggregation, layer 2 + fused bias/log_softmax ----------------
__global__ void k_agg2(const float* __restrict__ b2,
                       float* __restrict__ out_lsm,
                       float* __restrict__ out_logit,
                       long long nwork) {
    long long idx = (long long)blockIdx.x * blockDim.x + threadIdx.x;
    if (idx >= nwork) return;
    int node   = (int)(idx >> 4);
    int lane16 = (int)(idx & 15);
    int c      = lane16 << 2;
    bool active = (lane16 < 10);

    int beg = g_rowptr[node];
    int n   = g_cnt[node];

    float4 acc  = active ? *(const float4*)&g_logits[(size_t)node * NCLS + c]
                         : make_float4(0.f, 0.f, 0.f, 0.f);
    float4 acc2 = make_float4(0.f, 0.f, 0.f, 0.f);

    if (active) {
        int j = 0;
        for (; j + 3 < n; j += 4) {
            int2 e0 = g_csr[beg + j + 0];
            int2 e1 = g_csr[beg + j + 1];
            int2 e2 = g_csr[beg + j + 2];
            int2 e3 = g_csr[beg + j + 3];
            float4 v0 = __ldg((const float4*)&g_xw2[(size_t)e0.x * NCLS + c]);
            float4 v1 = __ldg((const float4*)&g_xw2[(size_t)e1.x * NCLS + c]);
            float4 v2 = __ldg((const float4*)&g_xw2[(size_t)e2.x * NCLS + c]);
            float4 v3 = __ldg((const float4*)&g_xw2[(size_t)e3.x * NCLS + c]);
            float n0 = __int_as_float(e0.y);
            float n1 = __int_as_float(e1.y);
            float n2 = __int_as_float(e2.y);
            float n3 = __int_as_float(e3.y);
            acc.x  = fmaf(v0.x, n0, acc.x);  acc.y  = fmaf(v0.y, n0, acc.y);
            acc.z  = fmaf(v0.z, n0, acc.z);  acc.w  = fmaf(v0.w, n0, acc.w);
            acc2.x = fmaf(v1.x, n1, acc2.x); acc2.y = fmaf(v1.y, n1, acc2.y);
            acc2.z = fmaf(v1.z, n1, acc2.z); acc2.w = fmaf(v1.w, n1, acc2.w);
            acc.x  = fmaf(v2.x, n2, acc.x);  acc.y  = fmaf(v2.y, n2, acc.y);
            acc.z  = fmaf(v2.z, n2, acc.z);  acc.w  = fmaf(v2.w, n2, acc.w);
            acc2.x = fmaf(v3.x, n3, acc2.x); acc2.y = fmaf(v3.y, n3, acc2.y);
            acc2.z = fmaf(v3.z, n3, acc2.z); acc2.w = fmaf(v3.w, n3, acc2.w);
        }
        for (; j < n; j++) {
            int2 e0 = g_csr[beg + j];
            float4 v0 = __ldg((const float4*)&g_xw2[(size_t)e0.x * NCLS + c]);
            float n0 = __int_as_float(e0.y);
            acc.x = fmaf(v0.x, n0, acc.x);
            acc.y = fmaf(v0.y, n0, acc.y);
            acc.z = fmaf(v0.z, n0, acc.z);
            acc.w = fmaf(v0.w, n0, acc.w);
        }
        acc.x += acc2.x; acc.y += acc2.y; acc.z += acc2.z; acc.w += acc2.w;
        float4 bv = *(const float4*)&b2[c];
        acc.x += bv.x; acc.y += bv.y; acc.z += bv.z; acc.w += bv.w;
    }

    const unsigned FM = 0xffffffffu;
    float lmax = active ? fmaxf(fmaxf(acc.x, acc.y), fmaxf(acc.z, acc.w)) : -INFINITY;
    #pragma unroll
    for (int off = 8; off > 0; off >>= 1)
        lmax = fmaxf(lmax, __shfl_xor_sync(FM, lmax, off, 16));

    float lsum = 0.0f;
    if (active) {
        lsum = expf(acc.x - lmax) + expf(acc.y - lmax)
             + expf(acc.z - lmax) + expf(acc.w - lmax);
    }
    #pragma unroll
    for (int off = 8; off > 0; off >>= 1)
        lsum += __shfl_xor_sync(FM, lsum, off, 16);

    float lse = lmax + logf(lsum);

    if (active) {
        if (out_logit)
            *(float4*)&out_logit[(size_t)node * NCLS + c] = acc;
        *(float4*)&out_lsm[(size_t)node * NCLS + c] =
            make_float4(acc.x - lse, acc.y - lse, acc.z - lse, acc.w - lse);
    }
}

// ---------------- launch ----------------
extern "C" void kernel_launch(void* const* d_in, const int* in_sizes, int n_in,
                              void* d_out, int out_size) {
    const float* x   = (const float*)d_in[0];
    const int*   ei  = (const int*)d_in[1];   // edge_index is int32
    const float* W1  = (const float*)d_in[2];
    const float* b1  = (const float*)d_in[3];
    const float* W2  = (const float*)d_in[4];
    const float* b2  = (const float*)d_in[5];

    const int E = in_sizes[1] / 2;
    const int* srcp = ei;
    const int* dstp = ei + E;

    float* out = (float*)d_out;
    float* out_lsm = out;
    float* out_logit = nullptr;
    if (out_size >= 2 * N_NODES * NCLS) {
        out_logit = out + (size_t)N_NODES * NCLS;
    }

    const int T = 256;
    const int nodeBlocks = (N_NODES + T - 1) / T;
    const int edgeBlocks = (E + T - 1) / T;

    // CSR build
    k_zero      <<<nodeBlocks, T>>>();
    k_count     <<<edgeBlocks, T>>>(srcp, dstp, E);
    k_dinv      <<<nodeBlocks, T>>>();
    k_scan_local<<<SCAN_NB, 256>>>();
    k_scan_bsum <<<1, 512>>>();
    k_scan_add  <<<SCAN_NB, 256>>>();
    k_fill      <<<edgeBlocks, T>>>(srcp, dstp, E);

    // layer 1
    k_gemm1<<<(N_NODES + 127) / 128, 256>>>(x, W1);
    long long w1 = (long long)N_NODES * 16;
    k_agg1<<<(int)((w1 + T - 1) / T), T>>>(w1);

    // layer 2 (agg2 fuses bias + log_softmax + output writes)
    k_gemm2<<<nodeBlocks, T>>>(W2, b1);
    long long w2 = (long long)N_NODES * 16;
    k_agg2<<<(int)((w2 + T - 1) / T), T>>>(b2, out_lsm, out_logit, w2);
}

// round 14
// speedup vs baseline: 1.6298x; 1.0240x over previous
#include <cuda_runtime.h>
#include <cuda_fp16.h>
#include <math.h>
#include <stdint.h>

#define N_NODES 100000
#define F_IN    500
#define HID     64
#define NCLS    40
#define E_MAX   2000000
#define SCAN_NB ((N_NODES + 255) / 256)   // 391

// ---------------- scratch (static device globals; no allocation) ----------------
__device__ alignas(256) float  g_dinv[N_NODES];
__device__ alignas(256) int    g_cnt   [N_NODES];
__device__ alignas(256) int    g_rowptr[N_NODES];
__device__ alignas(256) int    g_cursor[N_NODES];
__device__ alignas(256) int    g_bsum  [512];
__device__ alignas(16)  int2   g_csr   [E_MAX];      // {src, __float_as_int(norm)}
__device__ alignas(256) __half g_xw1h[(size_t)N_NODES * HID];   // x@W1, fp16 staged
__device__ alignas(256) float  g_h   [(size_t)N_NODES * HID];   // aggregated layer 1
__device__ alignas(256) __half g_xw2h[(size_t)N_NODES * NCLS];  // relu(h+b1)@W2, fp16

// ---------------- degree / csr build ----------------
__global__ void k_zero() {
    int i = blockIdx.x * blockDim.x + threadIdx.x;
    if (i < N_NODES) { g_cnt[i] = 0; g_cursor[i] = 0; }
}

__global__ void k_count(const int* __restrict__ src, const int* __restrict__ dst, int E) {
    int i = blockIdx.x * blockDim.x + threadIdx.x;
    if (i < E) {
        int s = src[i], d = dst[i];
        if ((unsigned)s < N_NODES && (unsigned)d < N_NODES) atomicAdd(&g_cnt[d], 1);
    }
}

__global__ void k_dinv() {
    int i = blockIdx.x * blockDim.x + threadIdx.x;
    if (i < N_NODES) g_dinv[i] = rsqrtf((float)(g_cnt[i] + 1));  // +1 self-loop
}

__global__ void k_scan_local() {
    __shared__ int sh[256];
    int tid = threadIdx.x;
    int i = blockIdx.x * 256 + tid;
    int v = (i < N_NODES) ? g_cnt[i] : 0;
    sh[tid] = v;
    __syncthreads();
    #pragma unroll
    for (int off = 1; off < 256; off <<= 1) {
        int t = (tid >= off) ? sh[tid - off] : 0;
        __syncthreads();
        sh[tid] += t;
        __syncthreads();
    }
    if (i < N_NODES) g_rowptr[i] = sh[tid] - v;
    if (tid == 255) g_bsum[blockIdx.x] = sh[255];
}

__global__ void k_scan_bsum() {
    __shared__ int sh[512];
    int tid = threadIdx.x;
    int v = (tid < SCAN_NB) ? g_bsum[tid] : 0;
    sh[tid] = v;
    __syncthreads();
    #pragma unroll
    for (int off = 1; off < 512; off <<= 1) {
        int t = (tid >= off) ? sh[tid - off] : 0;
        __syncthreads();
        sh[tid] += t;
        __syncthreads();
    }
    if (tid < SCAN_NB) g_bsum[tid] = sh[tid] - v;
}

__global__ void k_scan_add() {
    int i = blockIdx.x * 256 + threadIdx.x;
    if (i < N_NODES) g_rowptr[i] += g_bsum[blockIdx.x];
}

__global__ void k_fill(const int* __restrict__ src, const int* __restrict__ dst, int E) {
    int i = blockIdx.x * blockDim.x + threadIdx.x;
    if (i >= E) return;
    int s = src[i], d = dst[i];
    if ((unsigned)s >= N_NODES || (unsigned)d >= N_NODES) return;
    float nrm = g_dinv[s] * g_dinv[d];
    int pos = g_rowptr[d] + atomicAdd(&g_cursor[d], 1);
    g_csr[pos] = make_int2(s, __float_as_int(nrm));
}

// ---------------- GEMM1 (tf32 tensor cores) ----------------------------------------
// xw1 = x @ W1, written fp16. 128x64 tile, 8 warps, m16n8k8 tf32 mma.
__device__ __forceinline__ uint32_t f2tf32(float f) {
    uint32_t u;
    asm("cvt.rna.tf32.f32 %0, %1;" : "=r"(u) : "f"(f));
    return u;
}

#define XSS 36
#define WSS 72

__global__ void k_gemm1(const float* __restrict__ x, const float* __restrict__ W1) {
    __shared__ uint32_t xs[128 * XSS];  // xs[r*36 + k], tf32 bits
    __shared__ uint32_t ws[32 * WSS];   // ws[k*72 + n], tf32 bits
    const int tid  = threadIdx.x;
    const int lane = tid & 31;
    const int warp = tid >> 5;
    const int g = lane >> 2, t = lane & 3;
    const int row0 = blockIdx.x * 128;
    const int rw = warp * 16;

    float c[8][4] = {};

    for (int k0 = 0; k0 < 512; k0 += 32) {
        #pragma unroll
        for (int i = 0; i < 4; i++) {
            int linear = tid + i * 256;
            int r = linear >> 3, c4 = linear & 7;
            int gr = row0 + r, gc = k0 + c4 * 4;
            float4 v = make_float4(0.f, 0.f, 0.f, 0.f);
            if (gr < N_NODES && gc < F_IN)
                v = *(const float4*)&x[(size_t)gr * F_IN + gc];
            uint4 u = make_uint4(f2tf32(v.x), f2tf32(v.y), f2tf32(v.z), f2tf32(v.w));
            *(uint4*)&xs[r * XSS + c4 * 4] = u;
        }
        #pragma unroll
        for (int i = 0; i < 2; i++) {
            int linear = tid + i * 256;
            int r = linear >> 4, c4 = linear & 15;
            int gk = k0 + r;
            float4 v = make_float4(0.f, 0.f, 0.f, 0.f);
            if (gk < F_IN) v = *(const float4*)&W1[(size_t)gk * HID + c4 * 4];
            uint4 u = make_uint4(f2tf32(v.x), f2tf32(v.y), f2tf32(v.z), f2tf32(v.w));
            *(uint4*)&ws[r * WSS + c4 * 4] = u;
        }
        __syncthreads();

        #pragma unroll
        for (int ks = 0; ks < 4; ks++) {
            int kb = ks * 8;
            uint32_t a0 = xs[(rw + g    ) * XSS + kb + t    ];
            uint32_t a1 = xs[(rw + g + 8) * XSS + kb + t    ];
            uint32_t a2 = xs[(rw + g    ) * XSS + kb + t + 4];
            uint32_t a3 = xs[(rw + g + 8) * XSS + kb + t + 4];
            #pragma unroll
            for (int j = 0; j < 8; j++) {
                uint32_t b0 = ws[(kb + t    ) * WSS + j * 8 + g];
                uint32_t b1 = ws[(kb + t + 4) * WSS + j * 8 + g];
                asm volatile(
                    "mma.sync.aligned.m16n8k8.row.col.f32.tf32.tf32.f32 "
                    "{%0,%1,%2,%3}, {%4,%5,%6,%7}, {%8,%9}, {%0,%1,%2,%3};"
                    : "+f"(c[j][0]), "+f"(c[j][1]), "+f"(c[j][2]), "+f"(c[j][3])
                    : "r"(a0), "r"(a1), "r"(a2), "r"(a3), "r"(b0), "r"(b1));
            }
        }
        __syncthreads();
    }

    // epilogue: write fp16 only. c[j][0..1] -> row r0 cols j*8+2t..+1 ; c[j][2..3] -> r1
    int r0 = row0 + rw + g;
    int r1 = r0 + 8;
    #pragma unroll
    for (int j = 0; j < 8; j++) {
        int col = j * 8 + 2 * t;
        if (r0 < N_NODES)
            *(__half2*)&g_xw1h[(size_t)r0 * HID + col] = __floats2half2_rn(c[j][0], c[j][1]);
        if (r1 < N_NODES)
            *(__half2*)&g_xw1h[(size_t)r1 * HID + col] = __floats2half2_rn(c[j][2], c[j][3]);
    }
}

__device__ __forceinline__ float4 h4_to_f4(uint2 u) {
    float2 a = __half22float2(*(__half2*)&u.x);
    float2 b = __half22float2(*(__half2*)&u.y);
    return make_float4(a.x, a.y, b.x, b.y);
}

// ---------------- CSR aggregation, layer 1 (fp16 gathers) --------------------------
// 16 threads per node, 4 floats (8B fp16) each; 4-way unroll, dual accumulators.
__global__ void k_agg1(long long nwork) {
    long long idx = (long long)blockIdx.x * blockDim.x + threadIdx.x;
    if (idx >= nwork) return;
    int node = (int)(idx >> 4);
    int c = (int)(idx & 15) << 2;

    int beg = g_rowptr[node];
    int n   = g_cnt[node];
    float di = g_dinv[node];
    float d2 = di * di;

    // self-loop term from own fp16 row
    float4 sv = h4_to_f4(*(const uint2*)&g_xw1h[(size_t)node * HID + c]);
    float4 acc  = make_float4(sv.x * d2, sv.y * d2, sv.z * d2, sv.w * d2);
    float4 acc2 = make_float4(0.f, 0.f, 0.f, 0.f);

    int j = 0;
    for (; j + 3 < n; j += 4) {
        int2 e0 = g_csr[beg + j + 0];
        int2 e1 = g_csr[beg + j + 1];
        int2 e2 = g_csr[beg + j + 2];
        int2 e3 = g_csr[beg + j + 3];
        float4 v0 = h4_to_f4(__ldg((const uint2*)&g_xw1h[(size_t)e0.x * HID + c]));
        float4 v1 = h4_to_f4(__ldg((const uint2*)&g_xw1h[(size_t)e1.x * HID + c]));
        float4 v2 = h4_to_f4(__ldg((const uint2*)&g_xw1h[(size_t)e2.x * HID + c]));
        float4 v3 = h4_to_f4(__ldg((const uint2*)&g_xw1h[(size_t)e3.x * HID + c]));
        float n0 = __int_as_float(e0.y);
        float n1 = __int_as_float(e1.y);
        float n2 = __int_as_float(e2.y);
        float n3 = __int_as_float(e3.y);
        acc.x  = fmaf(v0.x, n0, acc.x);  acc.y  = fmaf(v0.y, n0, acc.y);
        acc.z  = fmaf(v0.z, n0, acc.z);  acc.w  = fmaf(v0.w, n0, acc.w);
        acc2.x = fmaf(v1.x, n1, acc2.x); acc2.y = fmaf(v1.y, n1, acc2.y);
        acc2.z = fmaf(v1.z, n1, acc2.z); acc2.w = fmaf(v1.w, n1, acc2.w);
        acc.x  = fmaf(v2.x, n2, acc.x);  acc.y  = fmaf(v2.y, n2, acc.y);
        acc.z  = fmaf(v2.z, n2, acc.z);  acc.w  = fmaf(v2.w, n2, acc.w);
        acc2.x = fmaf(v3.x, n3, acc2.x); acc2.y = fmaf(v3.y, n3, acc2.y);
        acc2.z = fmaf(v3.z, n3, acc2.z); acc2.w = fmaf(v3.w, n3, acc2.w);
    }
    for (; j < n; j++) {
        int2 e0 = g_csr[beg + j];
        float4 v0 = h4_to_f4(__ldg((const uint2*)&g_xw1h[(size_t)e0.x * HID + c]));
        float n0 = __int_as_float(e0.y);
        acc.x = fmaf(v0.x, n0, acc.x);
        acc.y = fmaf(v0.y, n0, acc.y);
        acc.z = fmaf(v0.z, n0, acc.z);
        acc.w = fmaf(v0.w, n0, acc.w);
    }

    acc.x += acc2.x; acc.y += acc2.y; acc.z += acc2.z; acc.w += acc2.w;
    *(float4*)&g_h[(size_t)node * HID + c] = acc;
}

// ---------------- GEMM2: xw2 = relu(g_h + b1) @ W2, written fp16 -------------------
__global__ void k_gemm2(const float* __restrict__ W2, const float* __restrict__ b1) {
    __shared__ float ws[HID * NCLS];
    __shared__ float bs[HID];
    int tid = threadIdx.x;
    for (int i = tid; i < HID * NCLS; i += 256) ws[i] = W2[i];
    if (tid < HID) bs[tid] = b1[tid];
    __syncthreads();

    int row = blockIdx.x * 256 + tid;
    if (row >= N_NODES) return;

    float a[HID];
    const float4* hp = (const float4*)&g_h[(size_t)row * HID];
    #pragma unroll
    for (int i = 0; i < HID / 4; i++) {
        float4 v = hp[i];
        a[i * 4 + 0] = fmaxf(v.x + bs[i * 4 + 0], 0.0f);
        a[i * 4 + 1] = fmaxf(v.y + bs[i * 4 + 1], 0.0f);
        a[i * 4 + 2] = fmaxf(v.z + bs[i * 4 + 2], 0.0f);
        a[i * 4 + 3] = fmaxf(v.w + bs[i * 4 + 3], 0.0f);
    }

    float acc[NCLS] = {};
    #pragma unroll 8
    for (int k = 0; k < HID; k++) {
        float ak = a[k];
        #pragma unroll
        for (int j = 0; j < NCLS; j += 4) {
            float4 w = *(const float4*)&ws[k * NCLS + j];
            acc[j + 0] += ak * w.x;
            acc[j + 1] += ak * w.y;
            acc[j + 2] += ak * w.z;
            acc[j + 3] += ak * w.w;
        }
    }

    __half* xo = &g_xw2h[(size_t)row * NCLS];
    #pragma unroll
    for (int j = 0; j < NCLS / 4; j++) {
        uint2 u;
        *(__half2*)&u.x = __floats2half2_rn(acc[j * 4 + 0], acc[j * 4 + 1]);
        *(__half2*)&u.y = __floats2half2_rn(acc[j * 4 + 2], acc[j * 4 + 3]);
        *(uint2*)&xo[j * 4] = u;
    }
}

// ---------------- CSR aggregation, layer 2 + fused bias/log_softmax ----------------
__global__ void k_agg2(const float* __restrict__ b2,
                       float* __restrict__ out_lsm,
                       float* __restrict__ out_logit,
                       long long nwork) {
    long long idx = (long long)blockIdx.x * blockDim.x + threadIdx.x;
    if (idx >= nwork) return;
    int node   = (int)(idx >> 4);
    int lane16 = (int)(idx & 15);
    int c      = lane16 << 2;
    bool active = (lane16 < 10);

    int beg = g_rowptr[node];
    int n   = g_cnt[node];
    float di = g_dinv[node];
    float d2 = di * di;

    float4 acc  = make_float4(0.f, 0.f, 0.f, 0.f);
    float4 acc2 = make_float4(0.f, 0.f, 0.f, 0.f);

    if (active) {
        float4 sv = h4_to_f4(*(const uint2*)&g_xw2h[(size_t)node * NCLS + c]);
        acc = make_float4(sv.x * d2, sv.y * d2, sv.z * d2, sv.w * d2);

        int j = 0;
        for (; j + 3 < n; j += 4) {
            int2 e0 = g_csr[beg + j + 0];
            int2 e1 = g_csr[beg + j + 1];
            int2 e2 = g_csr[beg + j + 2];
            int2 e3 = g_csr[beg + j + 3];
            float4 v0 = h4_to_f4(__ldg((const uint2*)&g_xw2h[(size_t)e0.x * NCLS + c]));
            float4 v1 = h4_to_f4(__ldg((const uint2*)&g_xw2h[(size_t)e1.x * NCLS + c]));
            float4 v2 = h4_to_f4(__ldg((const uint2*)&g_xw2h[(size_t)e2.x * NCLS + c]));
            float4 v3 = h4_to_f4(__ldg((const uint2*)&g_xw2h[(size_t)e3.x * NCLS + c]));
            float n0 = __int_as_float(e0.y);
            float n1 = __int_as_float(e1.y);
            float n2 = __int_as_float(e2.y);
            float n3 = __int_as_float(e3.y);
            acc.x  = fmaf(v0.x, n0, acc.x);  acc.y  = fmaf(v0.y, n0, acc.y);
            acc.z  = fmaf(v0.z, n0, acc.z);  acc.w  = fmaf(v0.w, n0, acc.w);
            acc2.x = fmaf(v1.x, n1, acc2.x); acc2.y = fmaf(v1.y, n1, acc2.y);
            acc2.z = fmaf(v1.z, n1, acc2.z); acc2.w = fmaf(v1.w, n1, acc2.w);
            acc.x  = fmaf(v2.x, n2, acc.x);  acc.y  = fmaf(v2.y, n2, acc.y);
            acc.z  = fmaf(v2.z, n2, acc.z);  acc.w  = fmaf(v2.w, n2, acc.w);
            acc2.x = fmaf(v3.x, n3, acc2.x); acc2.y = fmaf(v3.y, n3, acc2.y);
            acc2.z = fmaf(v3.z, n3, acc2.z); acc2.w = fmaf(v3.w, n3, acc2.w);
        }
        for (; j < n; j++) {
            int2 e0 = g_csr[beg + j];
            float4 v0 = h4_to_f4(__ldg((const uint2*)&g_xw2h[(size_t)e0.x * NCLS + c]));
            float n0 = __int_as_float(e0.y);
            acc.x = fmaf(v0.x, n0, acc.x);
            acc.y = fmaf(v0.y, n0, acc.y);
            acc.z = fmaf(v0.z, n0, acc.z);
            acc.w = fmaf(v0.w, n0, acc.w);
        }
        acc.x += acc2.x; acc.y += acc2.y; acc.z += acc2.z; acc.w += acc2.w;
        float4 bv = *(const float4*)&b2[c];
        acc.x += bv.x; acc.y += bv.y; acc.z += bv.z; acc.w += bv.w;
    }

    const unsigned FM = 0xffffffffu;
    float lmax = active ? fmaxf(fmaxf(acc.x, acc.y), fmaxf(acc.z, acc.w)) : -INFINITY;
    #pragma unroll
    for (int off = 8; off > 0; off >>= 1)
        lmax = fmaxf(lmax, __shfl_xor_sync(FM, lmax, off, 16));

    float lsum = 0.0f;
    if (active) {
        lsum = expf(acc.x - lmax) + expf(acc.y - lmax)
             + expf(acc.z - lmax) + expf(acc.w - lmax);
    }
    #pragma unroll
    for (int off = 8; off > 0; off >>= 1)
        lsum += __shfl_xor_sync(FM, lsum, off, 16);

    float lse = lmax + logf(lsum);

    if (active) {
        if (out_logit)
            *(float4*)&out_logit[(size_t)node * NCLS + c] = acc;
        *(float4*)&out_lsm[(size_t)node * NCLS + c] =
            make_float4(acc.x - lse, acc.y - lse, acc.z - lse, acc.w - lse);
    }
}

// ---------------- launch ----------------
extern "C" void kernel_launch(void* const* d_in, const int* in_sizes, int n_in,
                              void* d_out, int out_size) {
    const float* x   = (const float*)d_in[0];
    const int*   ei  = (const int*)d_in[1];   // edge_index is int32
    const float* W1  = (const float*)d_in[2];
    const float* b1  = (const float*)d_in[3];
    const float* W2  = (const float*)d_in[4];
    const float* b2  = (const float*)d_in[5];

    const int E = in_sizes[1] / 2;
    const int* srcp = ei;
    const int* dstp = ei + E;

    float* out = (float*)d_out;
    float* out_lsm = out;
    float* out_logit = nullptr;
    if (out_size >= 2 * N_NODES * NCLS) {
        out_logit = out + (size_t)N_NODES * NCLS;
    }

    const int T = 256;
    const int nodeBlocks = (N_NODES + T - 1) / T;
    const int edgeBlocks = (E + T - 1) / T;

    // CSR build
    k_zero      <<<nodeBlocks, T>>>();
    k_count     <<<edgeBlocks, T>>>(srcp, dstp, E);
    k_dinv      <<<nodeBlocks, T>>>();
    k_scan_local<<<SCAN_NB, 256>>>();
    k_scan_bsum <<<1, 512>>>();
    k_scan_add  <<<SCAN_NB, 256>>>();
    k_fill      <<<edgeBlocks, T>>>(srcp, dstp, E);

    // layer 1
    k_gemm1<<<(N_NODES + 127) / 128, 256>>>(x, W1);
    long long w1 = (long long)N_NODES * 16;
    k_agg1<<<(int)((w1 + T - 1) / T), T>>>(w1);

    // layer 2 (agg2 fuses bias + log_softmax + output writes)
    k_gemm2<<<nodeBlocks, T>>>(W2, b1);
    long long w2 = (long long)N_NODES * 16;
    k_agg2<<<(int)((w2 + T - 1) / T), T>>>(b2, out_lsm, out_logit, w2);
}

// round 15
// speedup vs baseline: 1.6587x; 1.0177x over previous
#include <cuda_runtime.h>
#include <cuda_fp16.h>
#include <math.h>
#include <stdint.h>

#define N_NODES 100000
#define F_IN    500
#define HID     64
#define NCLS    40
#define E_MAX   2000000
#define SCAN_NB ((N_NODES + 255) / 256)   // 391

// ---------------- scratch (static device globals; no allocation) ----------------
__device__ alignas(256) float  g_dinv[N_NODES];
__device__ alignas(256) int    g_cnt   [N_NODES];
__device__ alignas(256) int    g_rowptr[N_NODES];
__device__ alignas(256) int    g_cursor[N_NODES];
__device__ alignas(256) int    g_bsum  [512];
__device__ alignas(16)  int2   g_csr   [E_MAX];      // {src, __float_as_int(norm)}
__device__ alignas(256) __half g_xw1h[(size_t)N_NODES * HID];   // x@W1, fp16 staged
__device__ alignas(256) float  g_h   [(size_t)N_NODES * HID];   // aggregated layer 1
__device__ alignas(256) __half g_xw2h[(size_t)N_NODES * NCLS];  // relu(h+b1)@W2, fp16

// ---------------- degree / csr build ----------------
__global__ void k_zero() {
    int i = blockIdx.x * blockDim.x + threadIdx.x;
    if (i < N_NODES) { g_cnt[i] = 0; g_cursor[i] = 0; }
}

__global__ void k_count(const int* __restrict__ src, const int* __restrict__ dst, int E) {
    int i = blockIdx.x * blockDim.x + threadIdx.x;
    if (i < E) {
        int s = src[i], d = dst[i];
        if ((unsigned)s < N_NODES && (unsigned)d < N_NODES) atomicAdd(&g_cnt[d], 1);
    }
}

__global__ void k_dinv() {
    int i = blockIdx.x * blockDim.x + threadIdx.x;
    if (i < N_NODES) g_dinv[i] = rsqrtf((float)(g_cnt[i] + 1));  // +1 self-loop
}

__global__ void k_scan_local() {
    __shared__ int sh[256];
    int tid = threadIdx.x;
    int i = blockIdx.x * 256 + tid;
    int v = (i < N_NODES) ? g_cnt[i] : 0;
    sh[tid] = v;
    __syncthreads();
    #pragma unroll
    for (int off = 1; off < 256; off <<= 1) {
        int t = (tid >= off) ? sh[tid - off] : 0;
        __syncthreads();
        sh[tid] += t;
        __syncthreads();
    }
    if (i < N_NODES) g_rowptr[i] = sh[tid] - v;
    if (tid == 255) g_bsum[blockIdx.x] = sh[255];
}

__global__ void k_scan_bsum() {
    __shared__ int sh[512];
    int tid = threadIdx.x;
    int v = (tid < SCAN_NB) ? g_bsum[tid] : 0;
    sh[tid] = v;
    __syncthreads();
    #pragma unroll
    for (int off = 1; off < 512; off <<= 1) {
        int t = (tid >= off) ? sh[tid - off] : 0;
        __syncthreads();
        sh[tid] += t;
        __syncthreads();
    }
    if (tid < SCAN_NB) g_bsum[tid] = sh[tid] - v;
}

__global__ void k_scan_add() {
    int i = blockIdx.x * 256 + threadIdx.x;
    if (i < N_NODES) g_rowptr[i] += g_bsum[blockIdx.x];
}

__global__ void k_fill(const int* __restrict__ src, const int* __restrict__ dst, int E) {
    int i = blockIdx.x * blockDim.x + threadIdx.x;
    if (i >= E) return;
    int s = src[i], d = dst[i];
    if ((unsigned)s >= N_NODES || (unsigned)d >= N_NODES) return;
    float nrm = g_dinv[s] * g_dinv[d];
    int pos = g_rowptr[d] + atomicAdd(&g_cursor[d], 1);
    g_csr[pos] = make_int2(s, __float_as_int(nrm));
}

// ---------------- GEMM1 (tf32 tensor cores) ----------------------------------------
__device__ __forceinline__ uint32_t f2tf32(float f) {
    uint32_t u;
    asm("cvt.rna.tf32.f32 %0, %1;" : "=r"(u) : "f"(f));
    return u;
}

#define XSS 36
#define WSS 72

__global__ void k_gemm1(const float* __restrict__ x, const float* __restrict__ W1) {
    __shared__ uint32_t xs[128 * XSS];  // xs[r*36 + k], tf32 bits
    __shared__ uint32_t ws[32 * WSS];   // ws[k*72 + n], tf32 bits
    const int tid  = threadIdx.x;
    const int lane = tid & 31;
    const int warp = tid >> 5;
    const int g = lane >> 2, t = lane & 3;
    const int row0 = blockIdx.x * 128;
    const int rw = warp * 16;

    float c[8][4] = {};

    for (int k0 = 0; k0 < 512; k0 += 32) {
        #pragma unroll
        for (int i = 0; i < 4; i++) {
            int linear = tid + i * 256;
            int r = linear >> 3, c4 = linear & 7;
            int gr = row0 + r, gc = k0 + c4 * 4;
            float4 v = make_float4(0.f, 0.f, 0.f, 0.f);
            if (gr < N_NODES && gc < F_IN)
                v = *(const float4*)&x[(size_t)gr * F_IN + gc];
            uint4 u = make_uint4(f2tf32(v.x), f2tf32(v.y), f2tf32(v.z), f2tf32(v.w));
            *(uint4*)&xs[r * XSS + c4 * 4] = u;
        }
        #pragma unroll
        for (int i = 0; i < 2; i++) {
            int linear = tid + i * 256;
            int r = linear >> 4, c4 = linear & 15;
            int gk = k0 + r;
            float4 v = make_float4(0.f, 0.f, 0.f, 0.f);
            if (gk < F_IN) v = *(const float4*)&W1[(size_t)gk * HID + c4 * 4];
            uint4 u = make_uint4(f2tf32(v.x), f2tf32(v.y), f2tf32(v.z), f2tf32(v.w));
            *(uint4*)&ws[r * WSS + c4 * 4] = u;
        }
        __syncthreads();

        #pragma unroll
        for (int ks = 0; ks < 4; ks++) {
            int kb = ks * 8;
            uint32_t a0 = xs[(rw + g    ) * XSS + kb + t    ];
            uint32_t a1 = xs[(rw + g + 8) * XSS + kb + t    ];
            uint32_t a2 = xs[(rw + g    ) * XSS + kb + t + 4];
            uint32_t a3 = xs[(rw + g + 8) * XSS + kb + t + 4];
            #pragma unroll
            for (int j = 0; j < 8; j++) {
                uint32_t b0 = ws[(kb + t    ) * WSS + j * 8 + g];
                uint32_t b1 = ws[(kb + t + 4) * WSS + j * 8 + g];
                asm volatile(
                    "mma.sync.aligned.m16n8k8.row.col.f32.tf32.tf32.f32 "
                    "{%0,%1,%2,%3}, {%4,%5,%6,%7}, {%8,%9}, {%0,%1,%2,%3};"
                    : "+f"(c[j][0]), "+f"(c[j][1]), "+f"(c[j][2]), "+f"(c[j][3])
                    : "r"(a0), "r"(a1), "r"(a2), "r"(a3), "r"(b0), "r"(b1));
            }
        }
        __syncthreads();
    }

    int r0 = row0 + rw + g;
    int r1 = r0 + 8;
    #pragma unroll
    for (int j = 0; j < 8; j++) {
        int col = j * 8 + 2 * t;
        if (r0 < N_NODES)
            *(__half2*)&g_xw1h[(size_t)r0 * HID + col] = __floats2half2_rn(c[j][0], c[j][1]);
        if (r1 < N_NODES)
            *(__half2*)&g_xw1h[(size_t)r1 * HID + col] = __floats2half2_rn(c[j][2], c[j][3]);
    }
}

__device__ __forceinline__ float4 h4_to_f4(uint2 u) {
    float2 a = __half22float2(*(__half2*)&u.x);
    float2 b = __half22float2(*(__half2*)&u.y);
    return make_float4(a.x, a.y, b.x, b.y);
}

// ---------------- CSR aggregation, layer 1 -----------------------------------------
// ONE WARP per node: 16 column-lanes x 2 edge-halves. Each half walks its half of the
// edge list (4-way unrolled); halves combine via shfl_xor(16) at the end.
__global__ void k_agg1(long long nwork) {
    long long idx = (long long)blockIdx.x * blockDim.x + threadIdx.x;
    if (idx >= nwork) return;
    int node   = (int)(idx >> 5);
    int lane   = (int)(idx & 31);
    int lane16 = lane & 15;
    int half   = lane >> 4;
    int c      = lane16 << 2;

    int beg = g_rowptr[node];
    int n   = g_cnt[node];
    int nh  = (n + 1) >> 1;
    int j    = half ? nh : 0;
    int jend = half ? n  : nh;

    float4 acc, acc2 = make_float4(0.f, 0.f, 0.f, 0.f);
    if (half == 0) {
        float di = g_dinv[node];
        float d2 = di * di;
        float4 sv = h4_to_f4(*(const uint2*)&g_xw1h[(size_t)node * HID + c]);
        acc = make_float4(sv.x * d2, sv.y * d2, sv.z * d2, sv.w * d2);
    } else {
        acc = make_float4(0.f, 0.f, 0.f, 0.f);
    }

    for (; j + 3 < jend; j += 4) {
        int2 e0 = g_csr[beg + j + 0];
        int2 e1 = g_csr[beg + j + 1];
        int2 e2 = g_csr[beg + j + 2];
        int2 e3 = g_csr[beg + j + 3];
        float4 v0 = h4_to_f4(__ldg((const uint2*)&g_xw1h[(size_t)e0.x * HID + c]));
        float4 v1 = h4_to_f4(__ldg((const uint2*)&g_xw1h[(size_t)e1.x * HID + c]));
        float4 v2 = h4_to_f4(__ldg((const uint2*)&g_xw1h[(size_t)e2.x * HID + c]));
        float4 v3 = h4_to_f4(__ldg((const uint2*)&g_xw1h[(size_t)e3.x * HID + c]));
        float n0 = __int_as_float(e0.y);
        float n1 = __int_as_float(e1.y);
        float n2 = __int_as_float(e2.y);
        float n3 = __int_as_float(e3.y);
        acc.x  = fmaf(v0.x, n0, acc.x);  acc.y  = fmaf(v0.y, n0, acc.y);
        acc.z  = fmaf(v0.z, n0, acc.z);  acc.w  = fmaf(v0.w, n0, acc.w);
        acc2.x = fmaf(v1.x, n1, acc2.x); acc2.y = fmaf(v1.y, n1, acc2.y);
        acc2.z = fmaf(v1.z, n1, acc2.z); acc2.w = fmaf(v1.w, n1, acc2.w);
        acc.x  = fmaf(v2.x, n2, acc.x);  acc.y  = fmaf(v2.y, n2, acc.y);
        acc.z  = fmaf(v2.z, n2, acc.z);  acc.w  = fmaf(v2.w, n2, acc.w);
        acc2.x = fmaf(v3.x, n3, acc2.x); acc2.y = fmaf(v3.y, n3, acc2.y);
        acc2.z = fmaf(v3.z, n3, acc2.z); acc2.w = fmaf(v3.w, n3, acc2.w);
    }
    for (; j < jend; j++) {
        int2 e0 = g_csr[beg + j];
        float4 v0 = h4_to_f4(__ldg((const uint2*)&g_xw1h[(size_t)e0.x * HID + c]));
        float n0 = __int_as_float(e0.y);
        acc.x = fmaf(v0.x, n0, acc.x);
        acc.y = fmaf(v0.y, n0, acc.y);
        acc.z = fmaf(v0.z, n0, acc.z);
        acc.w = fmaf(v0.w, n0, acc.w);
    }

    acc.x += acc2.x; acc.y += acc2.y; acc.z += acc2.z; acc.w += acc2.w;

    // combine halves
    const unsigned FM = 0xffffffffu;
    acc.x += __shfl_xor_sync(FM, acc.x, 16);
    acc.y += __shfl_xor_sync(FM, acc.y, 16);
    acc.z += __shfl_xor_sync(FM, acc.z, 16);
    acc.w += __shfl_xor_sync(FM, acc.w, 16);

    if (half == 0)
        *(float4*)&g_h[(size_t)node * HID + c] = acc;
}

// ---------------- GEMM2: xw2 = relu(g_h + b1) @ W2, written fp16 -------------------
__global__ void k_gemm2(const float* __restrict__ W2, const float* __restrict__ b1) {
    __shared__ float ws[HID * NCLS];
    __shared__ float bs[HID];
    int tid = threadIdx.x;
    for (int i = tid; i < HID * NCLS; i += 256) ws[i] = W2[i];
    if (tid < HID) bs[tid] = b1[tid];
    __syncthreads();

    int row = blockIdx.x * 256 + tid;
    if (row >= N_NODES) return;

    float a[HID];
    const float4* hp = (const float4*)&g_h[(size_t)row * HID];
    #pragma unroll
    for (int i = 0; i < HID / 4; i++) {
        float4 v = hp[i];
        a[i * 4 + 0] = fmaxf(v.x + bs[i * 4 + 0], 0.0f);
        a[i * 4 + 1] = fmaxf(v.y + bs[i * 4 + 1], 0.0f);
        a[i * 4 + 2] = fmaxf(v.z + bs[i * 4 + 2], 0.0f);
        a[i * 4 + 3] = fmaxf(v.w + bs[i * 4 + 3], 0.0f);
    }

    float acc[NCLS] = {};
    #pragma unroll 8
    for (int k = 0; k < HID; k++) {
        float ak = a[k];
        #pragma unroll
        for (int j = 0; j < NCLS; j += 4) {
            float4 w = *(const float4*)&ws[k * NCLS + j];
            acc[j + 0] += ak * w.x;
            acc[j + 1] += ak * w.y;
            acc[j + 2] += ak * w.z;
            acc[j + 3] += ak * w.w;
        }
    }

    __half* xo = &g_xw2h[(size_t)row * NCLS];
    #pragma unroll
    for (int j = 0; j < NCLS / 4; j++) {
        uint2 u;
        *(__half2*)&u.x = __floats2half2_rn(acc[j * 4 + 0], acc[j * 4 + 1]);
        *(__half2*)&u.y = __floats2half2_rn(acc[j * 4 + 2], acc[j * 4 + 3]);
        *(uint2*)&xo[j * 4] = u;
    }
}

// ---------------- CSR aggregation, layer 2 + fused bias/log_softmax ----------------
// ONE WARP per node: lanes {0..9} and {16..25} gather the two edge-halves.
__global__ void k_agg2(const float* __restrict__ b2,
                       float* __restrict__ out_lsm,
                       float* __restrict__ out_logit,
                       long long nwork) {
    long long idx = (long long)blockIdx.x * blockDim.x + threadIdx.x;
    if (idx >= nwork) return;
    int node   = (int)(idx >> 5);
    int lane   = (int)(idx & 31);
    int lane16 = lane & 15;
    int half   = lane >> 4;
    int c      = lane16 << 2;
    bool active = (lane16 < 10);

    int beg = g_rowptr[node];
    int n   = g_cnt[node];
    int nh  = (n + 1) >> 1;
    int j    = half ? nh : 0;
    int jend = half ? n  : nh;

    float4 acc  = make_float4(0.f, 0.f, 0.f, 0.f);
    float4 acc2 = make_float4(0.f, 0.f, 0.f, 0.f);

    if (active) {
        if (half == 0) {
            float di = g_dinv[node];
            float d2 = di * di;
            float4 sv = h4_to_f4(*(const uint2*)&g_xw2h[(size_t)node * NCLS + c]);
            acc = make_float4(sv.x * d2, sv.y * d2, sv.z * d2, sv.w * d2);
        }
        for (; j + 3 < jend; j += 4) {
            int2 e0 = g_csr[beg + j + 0];
            int2 e1 = g_csr[beg + j + 1];
            int2 e2 = g_csr[beg + j + 2];
            int2 e3 = g_csr[beg + j + 3];
            float4 v0 = h4_to_f4(__ldg((const uint2*)&g_xw2h[(size_t)e0.x * NCLS + c]));
            float4 v1 = h4_to_f4(__ldg((const uint2*)&g_xw2h[(size_t)e1.x * NCLS + c]));
            float4 v2 = h4_to_f4(__ldg((const uint2*)&g_xw2h[(size_t)e2.x * NCLS + c]));
            float4 v3 = h4_to_f4(__ldg((const uint2*)&g_xw2h[(size_t)e3.x * NCLS + c]));
            float n0 = __int_as_float(e0.y);
            float n1 = __int_as_float(e1.y);
            float n2 = __int_as_float(e2.y);
            float n3 = __int_as_float(e3.y);
            acc.x  = fmaf(v0.x, n0, acc.x);  acc.y  = fmaf(v0.y, n0, acc.y);
            acc.z  = fmaf(v0.z, n0, acc.z);  acc.w  = fmaf(v0.w, n0, acc.w);
            acc2.x = fmaf(v1.x, n1, acc2.x); acc2.y = fmaf(v1.y, n1, acc2.y);
            acc2.z = fmaf(v1.z, n1, acc2.z); acc2.w = fmaf(v1.w, n1, acc2.w);
            acc.x  = fmaf(v2.x, n2, acc.x);  acc.y  = fmaf(v2.y, n2, acc.y);
            acc.z  = fmaf(v2.z, n2, acc.z);  acc.w  = fmaf(v2.w, n2, acc.w);
            acc2.x = fmaf(v3.x, n3, acc2.x); acc2.y = fmaf(v3.y, n3, acc2.y);
            acc2.z = fmaf(v3.z, n3, acc2.z); acc2.w = fmaf(v3.w, n3, acc2.w);
        }
        for (; j < jend; j++) {
            int2 e0 = g_csr[beg + j];
            float4 v0 = h4_to_f4(__ldg((const uint2*)&g_xw2h[(size_t)e0.x * NCLS + c]));
            float n0 = __int_as_float(e0.y);
            acc.x = fmaf(v0.x, n0, acc.x);
            acc.y = fmaf(v0.y, n0, acc.y);
            acc.z = fmaf(v0.z, n0, acc.z);
            acc.w = fmaf(v0.w, n0, acc.w);
        }
        acc.x += acc2.x; acc.y += acc2.y; acc.z += acc2.z; acc.w += acc2.w;
    }

    const unsigned FM = 0xffffffffu;
    // combine halves
    acc.x += __shfl_xor_sync(FM, acc.x, 16);
    acc.y += __shfl_xor_sync(FM, acc.y, 16);
    acc.z += __shfl_xor_sync(FM, acc.z, 16);
    acc.w += __shfl_xor_sync(FM, acc.w, 16);

    // bias (both halves compute identically from here; only half 0 writes)
    if (active) {
        float4 bv = *(const float4*)&b2[c];
        acc.x += bv.x; acc.y += bv.y; acc.z += bv.z; acc.w += bv.w;
    }

    float lmax = active ? fmaxf(fmaxf(acc.x, acc.y), fmaxf(acc.z, acc.w)) : -INFINITY;
    #pragma unroll
    for (int off = 8; off > 0; off >>= 1)
        lmax = fmaxf(lmax, __shfl_xor_sync(FM, lmax, off, 16));

    float lsum = 0.0f;
    if (active) {
        lsum = expf(acc.x - lmax) + expf(acc.y - lmax)
             + expf(acc.z - lmax) + expf(acc.w - lmax);
    }
    #pragma unroll
    for (int off = 8; off > 0; off >>= 1)
        lsum += __shfl_xor_sync(FM, lsum, off, 16);

    float lse = lmax + logf(lsum);

    if (active && half == 0) {
        if (out_logit)
            *(float4*)&out_logit[(size_t)node * NCLS + c] = acc;
        *(float4*)&out_lsm[(size_t)node * NCLS + c] =
            make_float4(acc.x - lse, acc.y - lse, acc.z - lse, acc.w - lse);
    }
}

// ---------------- launch ----------------
extern "C" void kernel_launch(void* const* d_in, const int* in_sizes, int n_in,
                              void* d_out, int out_size) {
    const float* x   = (const float*)d_in[0];
    const int*   ei  = (const int*)d_in[1];   // edge_index is int32
    const float* W1  = (const float*)d_in[2];
    const float* b1  = (const float*)d_in[3];
    const float* W2  = (const float*)d_in[4];
    const float* b2  = (const float*)d_in[5];

    const int E = in_sizes[1] / 2;
    const int* srcp = ei;
    const int* dstp = ei + E;

    float* out = (float*)d_out;
    float* out_lsm = out;
    float* out_logit = nullptr;
    if (out_size >= 2 * N_NODES * NCLS) {
        out_logit = out + (size_t)N_NODES * NCLS;
    }

    const int T = 256;
    const int nodeBlocks = (N_NODES + T - 1) / T;
    const int edgeBlocks = (E + T - 1) / T;

    // CSR build
    k_zero      <<<nodeBlocks, T>>>();
    k_count     <<<edgeBlocks, T>>>(srcp, dstp, E);
    k_dinv      <<<nodeBlocks, T>>>();
    k_scan_local<<<SCAN_NB, 256>>>();
    k_scan_bsum <<<1, 512>>>();
    k_scan_add  <<<SCAN_NB, 256>>>();
    k_fill      <<<edgeBlocks, T>>>(srcp, dstp, E);

    // layer 1
    k_gemm1<<<(N_NODES + 127) / 128, 256>>>(x, W1);
    long long w1 = (long long)N_NODES * 32;
    k_agg1<<<(int)((w1 + T - 1) / T), T>>>(w1);

    // layer 2 (agg2 fuses bias + log_softmax + output writes)
    k_gemm2<<<nodeBlocks, T>>>(W2, b1);
    long long w2 = (long long)N_NODES * 32;
    k_agg2<<<(int)((w2 + T - 1) / T), T>>>(b2, out_lsm, out_logit, w2);
}

// round 16
// speedup vs baseline: 1.9973x; 1.2041x over previous
#include <cuda_runtime.h>
#include <cuda_fp16.h>
#include <math.h>
#include <stdint.h>

#define N_NODES 100000
#define F_IN    500
#define HID     64
#define NCLS    40
#define E_MAX   2000000
#define SCAN_NB ((N_NODES + 255) / 256)   // 391
#define GB1     ((N_NODES + 127) / 128)   // 782 gemm1 blocks

// ---------------- scratch (static device globals; zero-initialized at load) --------
__device__ alignas(256) float  g_dinv[N_NODES];
__device__ alignas(256) int    g_cnt   [N_NODES];   // zeroed: load-time + k_cleanup
__device__ alignas(256) int    g_rowptr[N_NODES];   // block-local exclusive scan
__device__ alignas(256) int    g_cursor[N_NODES];   // zeroed: load-time + k_cleanup
__device__ alignas(256) int    g_bsum  [512];       // scanned block sums
__device__                int    g_scan_done;       // zeroed: load-time + k_cleanup
__device__ alignas(16)  int2   g_csr   [E_MAX];
__device__ alignas(256) __half g_xw1h[(size_t)N_NODES * HID];
__device__ alignas(256) float  g_h   [(size_t)N_NODES * HID];
__device__ alignas(256) __half g_xw2h[(size_t)N_NODES * NCLS];

// ---------------- GEMM1 (tf32) + edge counting, fused ------------------------------
__device__ __forceinline__ uint32_t f2tf32(float f) {
    uint32_t u;
    asm("cvt.rna.tf32.f32 %0, %1;" : "=r"(u) : "f"(f));
    return u;
}

#define XSS 36
#define WSS 72

__global__ void k_gemm1_count(const float* __restrict__ x, const float* __restrict__ W1,
                              const int* __restrict__ src, const int* __restrict__ dst,
                              int E) {
    __shared__ uint32_t xs[128 * XSS];
    __shared__ uint32_t ws[32 * WSS];

    if (blockIdx.x >= GB1) {
        // ---- edge-count path ----
        int e = (blockIdx.x - GB1) * 256 + threadIdx.x;
        if (e < E) {
            int s = src[e], d = dst[e];
            if ((unsigned)s < N_NODES && (unsigned)d < N_NODES) atomicAdd(&g_cnt[d], 1);
        }
        return;
    }

    // ---- gemm path ----
    const int tid  = threadIdx.x;
    const int lane = tid & 31;
    const int warp = tid >> 5;
    const int g = lane >> 2, t = lane & 3;
    const int row0 = blockIdx.x * 128;
    const int rw = warp * 16;

    float c[8][4] = {};

    for (int k0 = 0; k0 < 512; k0 += 32) {
        #pragma unroll
        for (int i = 0; i < 4; i++) {
            int linear = tid + i * 256;
            int r = linear >> 3, c4 = linear & 7;
            int gr = row0 + r, gc = k0 + c4 * 4;
            float4 v = make_float4(0.f, 0.f, 0.f, 0.f);
            if (gr < N_NODES && gc < F_IN)
                v = *(const float4*)&x[(size_t)gr * F_IN + gc];
            uint4 u = make_uint4(f2tf32(v.x), f2tf32(v.y), f2tf32(v.z), f2tf32(v.w));
            *(uint4*)&xs[r * XSS + c4 * 4] = u;
        }
        #pragma unroll
        for (int i = 0; i < 2; i++) {
            int linear = tid + i * 256;
            int r = linear >> 4, c4 = linear & 15;
            int gk = k0 + r;
            float4 v = make_float4(0.f, 0.f, 0.f, 0.f);
            if (gk < F_IN) v = *(const float4*)&W1[(size_t)gk * HID + c4 * 4];
            uint4 u = make_uint4(f2tf32(v.x), f2tf32(v.y), f2tf32(v.z), f2tf32(v.w));
            *(uint4*)&ws[r * WSS + c4 * 4] = u;
        }
        __syncthreads();

        #pragma unroll
        for (int ks = 0; ks < 4; ks++) {
            int kb = ks * 8;
            uint32_t a0 = xs[(rw + g    ) * XSS + kb + t    ];
            uint32_t a1 = xs[(rw + g + 8) * XSS + kb + t    ];
            uint32_t a2 = xs[(rw + g    ) * XSS + kb + t + 4];
            uint32_t a3 = xs[(rw + g + 8) * XSS + kb + t + 4];
            #pragma unroll
            for (int j = 0; j < 8; j++) {
                uint32_t b0 = ws[(kb + t    ) * WSS + j * 8 + g];
                uint32_t b1 = ws[(kb + t + 4) * WSS + j * 8 + g];
                asm volatile(
                    "mma.sync.aligned.m16n8k8.row.col.f32.tf32.tf32.f32 "
                    "{%0,%1,%2,%3}, {%4,%5,%6,%7}, {%8,%9}, {%0,%1,%2,%3};"
                    : "+f"(c[j][0]), "+f"(c[j][1]), "+f"(c[j][2]), "+f"(c[j][3])
                    : "r"(a0), "r"(a1), "r"(a2), "r"(a3), "r"(b0), "r"(b1));
            }
        }
        __syncthreads();
    }

    int r0 = row0 + rw + g;
    int r1 = r0 + 8;
    #pragma unroll
    for (int j = 0; j < 8; j++) {
        int col = j * 8 + 2 * t;
        if (r0 < N_NODES)
            *(__half2*)&g_xw1h[(size_t)r0 * HID + col] = __floats2half2_rn(c[j][0], c[j][1]);
        if (r1 < N_NODES)
            *(__half2*)&g_xw1h[(size_t)r1 * HID + col] = __floats2half2_rn(c[j][2], c[j][3]);
    }
}

// ---------------- single-pass scan (+ dinv); last block scans the block sums -------
__global__ void k_scan() {
    __shared__ int sh[256];
    __shared__ int isLast;
    int tid = threadIdx.x;
    int i = blockIdx.x * 256 + tid;
    int v = 0;
    if (i < N_NODES) {
        v = g_cnt[i];
        g_dinv[i] = rsqrtf((float)(v + 1));   // +1 self-loop
    }
    sh[tid] = v;
    __syncthreads();
    #pragma unroll
    for (int off = 1; off < 256; off <<= 1) {
        int t = (tid >= off) ? sh[tid - off] : 0;
        __syncthreads();
        sh[tid] += t;
        __syncthreads();
    }
    if (i < N_NODES) g_rowptr[i] = sh[tid] - v;   // exclusive within block
    if (tid == 255) g_bsum[blockIdx.x] = sh[255];

    // last arriving block serially scans the 391 block sums (exclusive, in place)
    __threadfence();
    if (tid == 0) {
        int old = atomicAdd(&g_scan_done, 1);
        isLast = (old == SCAN_NB - 1);
    }
    __syncthreads();
    if (isLast && tid == 0) {
        int run = 0;
        for (int b = 0; b < SCAN_NB; b++) {
            int t = g_bsum[b];
            g_bsum[b] = run;
            run += t;
        }
        __threadfence();
    }
}

// ---------------- fill CSR (rowptr = local + bsum) ---------------------------------
__global__ void k_fill(const int* __restrict__ src, const int* __restrict__ dst, int E) {
    int i = blockIdx.x * blockDim.x + threadIdx.x;
    if (i >= E) return;
    int s = src[i], d = dst[i];
    if ((unsigned)s >= N_NODES || (unsigned)d >= N_NODES) return;
    float nrm = g_dinv[s] * g_dinv[d];
    int pos = g_rowptr[d] + g_bsum[d >> 8] + atomicAdd(&g_cursor[d], 1);
    g_csr[pos] = make_int2(s, __float_as_int(nrm));
}

__device__ __forceinline__ float4 h4_to_f4(uint2 u) {
    float2 a = __half22float2(*(__half2*)&u.x);
    float2 b = __half22float2(*(__half2*)&u.y);
    return make_float4(a.x, a.y, b.x, b.y);
}

// ---------------- CSR aggregation, layer 1 (warp per node, 2 edge-halves) ----------
__global__ void k_agg1(long long nwork) {
    long long idx = (long long)blockIdx.x * blockDim.x + threadIdx.x;
    if (idx >= nwork) return;
    int node   = (int)(idx >> 5);
    int lane   = (int)(idx & 31);
    int lane16 = lane & 15;
    int half   = lane >> 4;
    int c      = lane16 << 2;

    int beg = g_rowptr[node] + g_bsum[node >> 8];
    int n   = g_cnt[node];
    int nh  = (n + 1) >> 1;
    int j    = half ? nh : 0;
    int jend = half ? n  : nh;

    float4 acc, acc2 = make_float4(0.f, 0.f, 0.f, 0.f);
    if (half == 0) {
        float di = g_dinv[node];
        float d2 = di * di;
        float4 sv = h4_to_f4(*(const uint2*)&g_xw1h[(size_t)node * HID + c]);
        acc = make_float4(sv.x * d2, sv.y * d2, sv.z * d2, sv.w * d2);
    } else {
        acc = make_float4(0.f, 0.f, 0.f, 0.f);
    }

    for (; j + 3 < jend; j += 4) {
        int2 e0 = g_csr[beg + j + 0];
        int2 e1 = g_csr[beg + j + 1];
        int2 e2 = g_csr[beg + j + 2];
        int2 e3 = g_csr[beg + j + 3];
        float4 v0 = h4_to_f4(__ldg((const uint2*)&g_xw1h[(size_t)e0.x * HID + c]));
        float4 v1 = h4_to_f4(__ldg((const uint2*)&g_xw1h[(size_t)e1.x * HID + c]));
        float4 v2 = h4_to_f4(__ldg((const uint2*)&g_xw1h[(size_t)e2.x * HID + c]));
        float4 v3 = h4_to_f4(__ldg((const uint2*)&g_xw1h[(size_t)e3.x * HID + c]));
        float n0 = __int_as_float(e0.y);
        float n1 = __int_as_float(e1.y);
        float n2 = __int_as_float(e2.y);
        float n3 = __int_as_float(e3.y);
        acc.x  = fmaf(v0.x, n0, acc.x);  acc.y  = fmaf(v0.y, n0, acc.y);
        acc.z  = fmaf(v0.z, n0, acc.z);  acc.w  = fmaf(v0.w, n0, acc.w);
        acc2.x = fmaf(v1.x, n1, acc2.x); acc2.y = fmaf(v1.y, n1, acc2.y);
        acc2.z = fmaf(v1.z, n1, acc2.z); acc2.w = fmaf(v1.w, n1, acc2.w);
        acc.x  = fmaf(v2.x, n2, acc.x);  acc.y  = fmaf(v2.y, n2, acc.y);
        acc.z  = fmaf(v2.z, n2, acc.z);  acc.w  = fmaf(v2.w, n2, acc.w);
        acc2.x = fmaf(v3.x, n3, acc2.x); acc2.y = fmaf(v3.y, n3, acc2.y);
        acc2.z = fmaf(v3.z, n3, acc2.z); acc2.w = fmaf(v3.w, n3, acc2.w);
    }
    for (; j < jend; j++) {
        int2 e0 = g_csr[beg + j];
        float4 v0 = h4_to_f4(__ldg((const uint2*)&g_xw1h[(size_t)e0.x * HID + c]));
        float n0 = __int_as_float(e0.y);
        acc.x = fmaf(v0.x, n0, acc.x);
        acc.y = fmaf(v0.y, n0, acc.y);
        acc.z = fmaf(v0.z, n0, acc.z);
        acc.w = fmaf(v0.w, n0, acc.w);
    }

    acc.x += acc2.x; acc.y += acc2.y; acc.z += acc2.z; acc.w += acc2.w;

    const unsigned FM = 0xffffffffu;
    acc.x += __shfl_xor_sync(FM, acc.x, 16);
    acc.y += __shfl_xor_sync(FM, acc.y, 16);
    acc.z += __shfl_xor_sync(FM, acc.z, 16);
    acc.w += __shfl_xor_sync(FM, acc.w, 16);

    if (half == 0)
        *(float4*)&g_h[(size_t)node * HID + c] = acc;
}

// ---------------- GEMM2: xw2 = relu(g_h + b1) @ W2, written fp16 -------------------
__global__ void k_gemm2(const float* __restrict__ W2, const float* __restrict__ b1) {
    __shared__ float ws[HID * NCLS];
    __shared__ float bs[HID];
    int tid = threadIdx.x;
    for (int i = tid; i < HID * NCLS; i += 256) ws[i] = W2[i];
    if (tid < HID) bs[tid] = b1[tid];
    __syncthreads();

    int row = blockIdx.x * 256 + tid;
    if (row >= N_NODES) return;

    float a[HID];
    const float4* hp = (const float4*)&g_h[(size_t)row * HID];
    #pragma unroll
    for (int i = 0; i < HID / 4; i++) {
        float4 v = hp[i];
        a[i * 4 + 0] = fmaxf(v.x + bs[i * 4 + 0], 0.0f);
        a[i * 4 + 1] = fmaxf(v.y + bs[i * 4 + 1], 0.0f);
        a[i * 4 + 2] = fmaxf(v.z + bs[i * 4 + 2], 0.0f);
        a[i * 4 + 3] = fmaxf(v.w + bs[i * 4 + 3], 0.0f);
    }

    float acc[NCLS] = {};
    #pragma unroll 8
    for (int k = 0; k < HID; k++) {
        float ak = a[k];
        #pragma unroll
        for (int j = 0; j < NCLS; j += 4) {
            float4 w = *(const float4*)&ws[k * NCLS + j];
            acc[j + 0] += ak * w.x;
            acc[j + 1] += ak * w.y;
            acc[j + 2] += ak * w.z;
            acc[j + 3] += ak * w.w;
        }
    }

    __half* xo = &g_xw2h[(size_t)row * NCLS];
    #pragma unroll
    for (int j = 0; j < NCLS / 4; j++) {
        uint2 u;
        *(__half2*)&u.x = __floats2half2_rn(acc[j * 4 + 0], acc[j * 4 + 1]);
        *(__half2*)&u.y = __floats2half2_rn(acc[j * 4 + 2], acc[j * 4 + 3]);
        *(uint2*)&xo[j * 4] = u;
    }
}

// ---------------- CSR aggregation, layer 2 + fused bias/log_softmax ----------------
__global__ void k_agg2(const float* __restrict__ b2,
                       float* __restrict__ out_lsm,
                       float* __restrict__ out_logit,
                       long long nwork) {
    long long idx = (long long)blockIdx.x * blockDim.x + threadIdx.x;
    if (idx >= nwork) return;
    int node   = (int)(idx >> 5);
    int lane   = (int)(idx & 31);
    int lane16 = lane & 15;
    int half   = lane >> 4;
    int c      = lane16 << 2;
    bool active = (lane16 < 10);

    int beg = g_rowptr[node] + g_bsum[node >> 8];
    int n   = g_cnt[node];
    int nh  = (n + 1) >> 1;
    int j    = half ? nh : 0;
    int jend = half ? n  : nh;

    float4 acc  = make_float4(0.f, 0.f, 0.f, 0.f);
    float4 acc2 = make_float4(0.f, 0.f, 0.f, 0.f);

    if (active) {
        if (half == 0) {
            float di = g_dinv[node];
            float d2 = di * di;
            float4 sv = h4_to_f4(*(const uint2*)&g_xw2h[(size_t)node * NCLS + c]);
            acc = make_float4(sv.x * d2, sv.y * d2, sv.z * d2, sv.w * d2);
        }
        for (; j + 3 < jend; j += 4) {
            int2 e0 = g_csr[beg + j + 0];
            int2 e1 = g_csr[beg + j + 1];
            int2 e2 = g_csr[beg + j + 2];
            int2 e3 = g_csr[beg + j + 3];
            float4 v0 = h4_to_f4(__ldg((const uint2*)&g_xw2h[(size_t)e0.x * NCLS + c]));
            float4 v1 = h4_to_f4(__ldg((const uint2*)&g_xw2h[(size_t)e1.x * NCLS + c]));
            float4 v2 = h4_to_f4(__ldg((const uint2*)&g_xw2h[(size_t)e2.x * NCLS + c]));
            float4 v3 = h4_to_f4(__ldg((const uint2*)&g_xw2h[(size_t)e3.x * NCLS + c]));
            float n0 = __int_as_float(e0.y);
            float n1 = __int_as_float(e1.y);
            float n2 = __int_as_float(e2.y);
            float n3 = __int_as_float(e3.y);
            acc.x  = fmaf(v0.x, n0, acc.x);  acc.y  = fmaf(v0.y, n0, acc.y);
            acc.z  = fmaf(v0.z, n0, acc.z);  acc.w  = fmaf(v0.w, n0, acc.w);
            acc2.x = fmaf(v1.x, n1, acc2.x); acc2.y = fmaf(v1.y, n1, acc2.y);
            acc2.z = fmaf(v1.z, n1, acc2.z); acc2.w = fmaf(v1.w, n1, acc2.w);
            acc.x  = fmaf(v2.x, n2, acc.x);  acc.y  = fmaf(v2.y, n2, acc.y);
            acc.z  = fmaf(v2.z, n2, acc.z);  acc.w  = fmaf(v2.w, n2, acc.w);
            acc2.x = fmaf(v3.x, n3, acc2.x); acc2.y = fmaf(v3.y, n3, acc2.y);
            acc2.z = fmaf(v3.z, n3, acc2.z); acc2.w = fmaf(v3.w, n3, acc2.w);
        }
        for (; j < jend; j++) {
            int2 e0 = g_csr[beg + j];
            float4 v0 = h4_to_f4(__ldg((const uint2*)&g_xw2h[(size_t)e0.x * NCLS + c]));
            float n0 = __int_as_float(e0.y);
            acc.x = fmaf(v0.x, n0, acc.x);
            acc.y = fmaf(v0.y, n0, acc.y);
            acc.z = fmaf(v0.z, n0, acc.z);
            acc.w = fmaf(v0.w, n0, acc.w);
        }
        acc.x += acc2.x; acc.y += acc2.y; acc.z += acc2.z; acc.w += acc2.w;
    }

    const unsigned FM = 0xffffffffu;
    acc.x += __shfl_xor_sync(FM, acc.x, 16);
    acc.y += __shfl_xor_sync(FM, acc.y, 16);
    acc.z += __shfl_xor_sync(FM, acc.z, 16);
    acc.w += __shfl_xor_sync(FM, acc.w, 16);

    if (active) {
        float4 bv = *(const float4*)&b2[c];
        acc.x += bv.x; acc.y += bv.y; acc.z += bv.z; acc.w += bv.w;
    }

    float lmax = active ? fmaxf(fmaxf(acc.x, acc.y), fmaxf(acc.z, acc.w)) : -INFINITY;
    #pragma unroll
    for (int off = 8; off > 0; off >>= 1)
        lmax = fmaxf(lmax, __shfl_xor_sync(FM, lmax, off, 16));

    float lsum = 0.0f;
    if (active) {
        lsum = expf(acc.x - lmax) + expf(acc.y - lmax)
             + expf(acc.z - lmax) + expf(acc.w - lmax);
    }
    #pragma unroll
    for (int off = 8; off > 0; off >>= 1)
        lsum += __shfl_xor_sync(FM, lsum, off, 16);

    float lse = lmax + logf(lsum);

    if (active && half == 0) {
        if (out_logit)
            *(float4*)&out_logit[(size_t)node * NCLS + c] = acc;
        *(float4*)&out_lsm[(size_t)node * NCLS + c] =
            make_float4(acc.x - lse, acc.y - lse, acc.z - lse, acc.w - lse);
    }
}

// ---------------- cleanup: restore zeroed state for the next replay ----------------
__global__ void k_cleanup() {
    int i = blockIdx.x * blockDim.x + threadIdx.x;
    if (i < N_NODES) { g_cnt[i] = 0; g_cursor[i] = 0; }
    if (i == 0) g_scan_done = 0;
}

// ---------------- launch ----------------
extern "C" void kernel_launch(void* const* d_in, const int* in_sizes, int n_in,
                              void* d_out, int out_size) {
    const float* x   = (const float*)d_in[0];
    const int*   ei  = (const int*)d_in[1];   // edge_index is int32
    const float* W1  = (const float*)d_in[2];
    const float* b1  = (const float*)d_in[3];
    const float* W2  = (const float*)d_in[4];
    const float* b2  = (const float*)d_in[5];

    const int E = in_sizes[1] / 2;
    const int* srcp = ei;
    const int* dstp = ei + E;

    float* out = (float*)d_out;
    float* out_lsm = out;
    float* out_logit = nullptr;
    if (out_size >= 2 * N_NODES * NCLS) {
        out_logit = out + (size_t)N_NODES * NCLS;
    }

    const int T = 256;
    const int nodeBlocks = (N_NODES + T - 1) / T;
    const int edgeBlocks = (E + T - 1) / T;

    // 1: gemm1 + edge count (fused, independent work)
    k_gemm1_count<<<GB1 + edgeBlocks, T>>>(x, W1, srcp, dstp, E);
    // 2: single-pass scan (+ dinv)
    k_scan<<<SCAN_NB, T>>>();
    // 3: fill CSR
    k_fill<<<edgeBlocks, T>>>(srcp, dstp, E);
    // 4: aggregation layer 1  (ncu capture lands here)
    long long w1 = (long long)N_NODES * 32;
    k_agg1<<<(int)((w1 + T - 1) / T), T>>>(w1);
    // 5: gemm2
    k_gemm2<<<nodeBlocks, T>>>(W2, b1);
    // 6: aggregation layer 2 + bias + log_softmax
    long long w2 = (long long)N_NODES * 32;
    k_agg2<<<(int)((w2 + T - 1) / T), T>>>(b2, out_lsm, out_logit, w2);
    // 7: restore zeroed counters for next replay
    k_cleanup<<<nodeBlocks, T>>>();
}